// round 9
// baseline (speedup 1.0000x reference)
#include <cuda_runtime.h>
#include <math.h>
#include <stdint.h>

// ---------------- problem constants ----------------
#define D_   1024
#define H_   8
#define E_   128
#define B_   4
#define S_   2048
#define NT_  (B_ * S_)
#define EPS_ 1e-6f

// ---------------- device scratch ----------------
__device__ float g_mod [NT_ * D_];
__device__ float g_h   [NT_ * D_];
__device__ float g_q   [NT_ * D_];
__device__ float g_k   [NT_ * D_];
__device__ float g_v   [NT_ * D_];
__device__ float g_mod2[NT_ * D_];
__device__ float g_h2  [NT_ * D_];

__device__ __forceinline__ float elu1(float x) { return x > 0.f ? x : expm1f(x); }

__device__ __forceinline__ float f2tf(float f) {
  uint32_t u;
  asm("cvt.rna.tf32.f32 %0, %1;" : "=r"(u) : "f"(f));
  return __uint_as_float(u);
}
__device__ __forceinline__ float4 tf32x4(float4 v) {
  return make_float4(f2tf(v.x), f2tf(v.y), f2tf(v.z), f2tf(v.w));
}

__device__ __forceinline__ void mma_tf32(float* d, const uint32_t* a, const uint32_t* b) {
  asm volatile(
      "mma.sync.aligned.m16n8k8.row.col.f32.tf32.tf32.f32 "
      "{%0,%1,%2,%3}, {%4,%5,%6,%7}, {%8,%9}, {%0,%1,%2,%3};"
      : "+f"(d[0]), "+f"(d[1]), "+f"(d[2]), "+f"(d[3])
      : "r"(a[0]), "r"(a[1]), "r"(a[2]), "r"(a[3]), "r"(b[0]), "r"(b[1]));
}

// ============================================================
// TF32 tensor-core GEMM (R2 core): 128x128 block tile, K-tile 32.
// 256 threads = 8 warps (2 x 4), warp tile 64x32.
// ============================================================
#define GBM 128
#define GBN 128
#define GBK 32
#define LDA_S 36
#define LDB_S 136

template <bool FFN>
__device__ __forceinline__ void gemm_tf32_core(
    const float* __restrict__ A, int lda,
    const float* __restrict__ Bm, int ldb,
    float* __restrict__ C, int ldc, int K,
    const float* __restrict__ bias, const float* __restrict__ resid) {
  __shared__ float As[GBM * LDA_S];
  __shared__ float Bs[GBK * LDB_S];

  const int t = threadIdx.x;
  const int lane = t & 31, wid = t >> 5;
  const int g = lane >> 2, tg = lane & 3;
  const int wr = wid >> 2, wc = wid & 3;

  const int a_c = (t & 7) * 4;   // 0..28
  const int a_r = t >> 3;        // 0..31
  const int b_c = (t & 31) * 4;  // 0..124
  const int b_r = t >> 5;        // 0..7

  float acc[4][4][4];
#pragma unroll
  for (int i = 0; i < 4; i++)
#pragma unroll
    for (int j = 0; j < 4; j++)
#pragma unroll
      for (int r = 0; r < 4; r++) acc[i][j][r] = 0.f;

  for (int k0 = 0; k0 < K; k0 += GBK) {
#pragma unroll
    for (int i = 0; i < 4; i++) {
      int r = a_r + i * 32;
      float4 v = *(const float4*)(A + (size_t)r * lda + k0 + a_c);
      *(float4*)&As[r * LDA_S + a_c] = tf32x4(v);
    }
#pragma unroll
    for (int i = 0; i < 4; i++) {
      int r = b_r + i * 8;
      float4 v = *(const float4*)(Bm + (size_t)(k0 + r) * ldb + b_c);
      *(float4*)&Bs[r * LDB_S + b_c] = tf32x4(v);
    }
    __syncthreads();

    const uint32_t* as = (const uint32_t*)As;
    const uint32_t* bs = (const uint32_t*)Bs;
#pragma unroll
    for (int kk = 0; kk < GBK; kk += 8) {
      uint32_t af[4][4], bf[4][2];
#pragma unroll
      for (int i = 0; i < 4; i++) {
        int r0 = wr * 64 + i * 16;
        af[i][0] = as[(r0 + g) * LDA_S + kk + tg];
        af[i][1] = as[(r0 + g + 8) * LDA_S + kk + tg];
        af[i][2] = as[(r0 + g) * LDA_S + kk + tg + 4];
        af[i][3] = as[(r0 + g + 8) * LDA_S + kk + tg + 4];
      }
#pragma unroll
      for (int j = 0; j < 4; j++) {
        int c0 = wc * 32 + j * 8;
        bf[j][0] = bs[(kk + tg) * LDB_S + c0 + g];
        bf[j][1] = bs[(kk + tg + 4) * LDB_S + c0 + g];
      }
#pragma unroll
      for (int i = 0; i < 4; i++)
#pragma unroll
        for (int j = 0; j < 4; j++) mma_tf32(acc[i][j], af[i], bf[j]);
    }
    __syncthreads();
  }

  // epilogue
#pragma unroll
  for (int i = 0; i < 4; i++) {
    int rA = wr * 64 + i * 16 + g;
    int rB = rA + 8;
#pragma unroll
    for (int j = 0; j < 4; j++) {
      int c = wc * 32 + j * 8 + 2 * tg;
      float2 o0 = make_float2(acc[i][j][0], acc[i][j][1]);
      float2 o1 = make_float2(acc[i][j][2], acc[i][j][3]);
      if (FFN) {
        float2 bv = *(const float2*)(bias + c);
        float2 r0 = *(const float2*)(resid + (size_t)rA * ldc + c);
        float2 r1 = *(const float2*)(resid + (size_t)rB * ldc + c);
        o0.x = r0.x + elu1(o0.x + bv.x);
        o0.y = r0.y + elu1(o0.y + bv.y);
        o1.x = r1.x + elu1(o1.x + bv.x);
        o1.y = r1.y + elu1(o1.y + bv.y);
      }
      *(float2*)(C + (size_t)rA * ldc + c) = o0;
      *(float2*)(C + (size_t)rB * ldc + c) = o1;
    }
  }
}

__global__ void __launch_bounds__(256) k_gemm_dense(const float* __restrict__ A,
                                                    const float* __restrict__ W,
                                                    float* __restrict__ C) {
  const size_t moff = (size_t)blockIdx.y * GBM * D_;
  gemm_tf32_core<false>(A + moff, D_, W + blockIdx.x * GBN, D_,
                        C + moff + blockIdx.x * GBN, D_, D_, nullptr, nullptr);
}

__global__ void __launch_bounds__(256) k_gemm_ffn(const float* __restrict__ A,
                                                  const float* __restrict__ W,
                                                  const float* __restrict__ bias,
                                                  const float* __restrict__ resid,
                                                  float* __restrict__ C) {
  const size_t moff = (size_t)blockIdx.y * GBM * D_;
  const size_t off = moff + blockIdx.x * GBN;
  gemm_tf32_core<true>(A + moff, D_, W + blockIdx.x * GBN, D_, C + off, D_, D_,
                       bias + blockIdx.x * GBN, resid + off);
}

__global__ void __launch_bounds__(256) k_gemm_qkv(const float* __restrict__ Hm,
                                                  const float* __restrict__ Wq,
                                                  const float* __restrict__ Wk,
                                                  const float* __restrict__ Wv,
                                                  float* __restrict__ Oq,
                                                  float* __restrict__ Ok,
                                                  float* __restrict__ Ov) {
  const int which = blockIdx.z;
  const float* W = which == 0 ? Wq : (which == 1 ? Wk : Wv);
  float* Out = which == 0 ? Oq : (which == 1 ? Ok : Ov);
  const int bh = blockIdx.y;
  const int b = bh >> 3, h = bh & 7;
  const float* A = Hm + ((size_t)b * S_ + (size_t)blockIdx.x * GBM) * D_ + h * E_;
  const float* Wp = W + h * E_ * E_;
  float* C = Out + ((size_t)bh * S_ + (size_t)blockIdx.x * GBM) * E_;
  gemm_tf32_core<false>(A, D_, Wp, E_, C, E_, E_, nullptr, nullptr);
}

// ============================================================
// LayerNorm over last dim (1024), one block per row
// ============================================================
__global__ void __launch_bounds__(256) k_ln(const float* __restrict__ in,
                                            float* __restrict__ out,
                                            const float* __restrict__ gamma,
                                            const float* __restrict__ beta) {
  const size_t row = blockIdx.x;
  const int t = threadIdx.x;
  float4 v = ((const float4*)(in + row * D_))[t];
  float s  = v.x + v.y + v.z + v.w;
  float s2 = v.x * v.x + v.y * v.y + v.z * v.z + v.w * v.w;
#pragma unroll
  for (int off = 16; off; off >>= 1) {
    s  += __shfl_xor_sync(0xffffffffu, s, off);
    s2 += __shfl_xor_sync(0xffffffffu, s2, off);
  }
  __shared__ float sb[16];
  if ((t & 31) == 0) { sb[t >> 5] = s; sb[(t >> 5) + 8] = s2; }
  __syncthreads();
  float tot = 0.f, tot2 = 0.f;
#pragma unroll
  for (int i = 0; i < 8; i++) { tot += sb[i]; tot2 += sb[i + 8]; }
  const float mean = tot * (1.f / D_);
  const float var  = tot2 * (1.f / D_) - mean * mean;
  const float inv  = rsqrtf(var + EPS_);
  float4 gm = ((const float4*)gamma)[t];
  float4 bb = ((const float4*)beta)[t];
  float4 o;
  o.x = (v.x - mean) * inv * gm.x + bb.x;
  o.y = (v.y - mean) * inv * gm.y + bb.y;
  o.z = (v.z - mean) * inv * gm.z + bb.z;
  o.w = (v.w - mean) * inv * gm.w + bb.w;
  ((float4*)(out + row * D_))[t] = o;
}

// ============================================================
// Flash attention, QT=128, KT=64, 512 threads = 16 warps (4x4).
// Phase A (scores 128x64): warp tile 32x16.
// Phase B (O += P V, 128x128): warp tile 32x32.
// Convert-at-fill tf32, parallel softmax (4 thr/row), fused residual.
// ============================================================
#define QT 128
#define KTT 64
#define NKT (S_ / KTT)
#define LQ 132
#define LK 132
#define LV 136
#define LP 68
#define ATTN_SMEM ((QT * LQ + KTT * LK + KTT * LV + QT * LP + 3 * QT) * 4)

__global__ void __launch_bounds__(512) k_attn(const float* __restrict__ Qg,
                                              const float* __restrict__ Kg,
                                              const float* __restrict__ Vg,
                                              const float* __restrict__ modin,
                                              float* __restrict__ modout) {
  extern __shared__ float sm[];
  float* q_s = sm;                          // [QT][LQ]
  float* k_s = q_s + QT * LQ;               // [KTT][LK]
  float* v_s = k_s + KTT * LK;              // [KTT][LV]
  float* p_s = v_s + KTT * LV;              // [QT][LP]
  float* alpha_s = p_s + QT * LP;           // [QT]
  float* l_s = alpha_s + QT;                // [QT]
  float* m_s = alpha_s + 2 * QT;            // [QT]

  const int t = threadIdx.x;
  const int lane = t & 31, wid = t >> 5;
  const int g = lane >> 2, tg = lane & 3;
  const int wr = wid >> 2, wc = wid & 3;    // 4 x 4 warp grid

  const int q0 = blockIdx.x * QT;
  const int h = blockIdx.y, b = blockIdx.z;
  const size_t bh = (size_t)b * H_ + h;

  const float* Kp = Kg + bh * S_ * E_;
  const float* Vp = Vg + bh * S_ * E_;

  const int ldrow = t >> 5, ldcol = (t & 31) * 4;   // 16 rows per pass

  // load + convert Q tile once (128 rows)
  {
    const float* Qp = Qg + (bh * S_ + q0) * E_;
#pragma unroll
    for (int i = 0; i < 8; i++) {
      int r = ldrow + i * 16;
      float4 v = *(const float4*)(Qp + (size_t)r * E_ + ldcol);
      *(float4*)&q_s[r * LQ + ldcol] = tf32x4(v);
    }
  }

  if (t < QT) { m_s[t] = -1e30f; l_s[t] = 0.f; }

  float o[2][4][4];
#pragma unroll
  for (int i = 0; i < 2; i++)
#pragma unroll
    for (int j = 0; j < 4; j++)
#pragma unroll
      for (int r = 0; r < 4; r++) o[i][j][r] = 0.f;

  for (int kt = 0; kt < NKT; kt++) {
    if (kt) __syncthreads();    // protect K/V/p_s reuse
    {
      const float* kb = Kp + (size_t)kt * KTT * E_;
      const float* vb = Vp + (size_t)kt * KTT * E_;
#pragma unroll
      for (int i = 0; i < 4; i++) {
        int r = ldrow + i * 16;
        float4 kv = *(const float4*)(kb + (size_t)r * E_ + ldcol);
        float4 vv = *(const float4*)(vb + (size_t)r * E_ + ldcol);
        *(float4*)&k_s[r * LK + ldcol] = tf32x4(kv);
        *(float4*)&v_s[r * LV + ldcol] = tf32x4(vv);
      }
    }
    __syncthreads();

    // ---- phase A: scores = Q K^T (128x64), warp tile 32x16 ----
    float sc[2][2][4];
#pragma unroll
    for (int i = 0; i < 2; i++)
#pragma unroll
      for (int j = 0; j < 2; j++)
#pragma unroll
        for (int r = 0; r < 4; r++) sc[i][j][r] = 0.f;

    const uint32_t* qs = (const uint32_t*)q_s;
    const uint32_t* ks = (const uint32_t*)k_s;
#pragma unroll
    for (int kk = 0; kk < E_; kk += 8) {
      uint32_t af[2][4], bf[2][2];
#pragma unroll
      for (int i = 0; i < 2; i++) {
        int r0 = wr * 32 + i * 16;
        af[i][0] = qs[(r0 + g) * LQ + kk + tg];
        af[i][1] = qs[(r0 + g + 8) * LQ + kk + tg];
        af[i][2] = qs[(r0 + g) * LQ + kk + tg + 4];
        af[i][3] = qs[(r0 + g + 8) * LQ + kk + tg + 4];
      }
#pragma unroll
      for (int j = 0; j < 2; j++) {
        int c0 = wc * 16 + j * 8;
        bf[j][0] = ks[(c0 + g) * LK + kk + tg];
        bf[j][1] = ks[(c0 + g) * LK + kk + tg + 4];
      }
#pragma unroll
      for (int i = 0; i < 2; i++)
#pragma unroll
        for (int j = 0; j < 2; j++) mma_tf32(sc[i][j], af[i], bf[j]);
    }

    // scatter raw scores to p_s
#pragma unroll
    for (int i = 0; i < 2; i++) {
      int rA = wr * 32 + i * 16 + g;
#pragma unroll
      for (int j = 0; j < 2; j++) {
        int c = wc * 16 + j * 8 + 2 * tg;
        *(float2*)&p_s[rA * LP + c] = make_float2(sc[i][j][0], sc[i][j][1]);
        *(float2*)&p_s[(rA + 8) * LP + c] = make_float2(sc[i][j][2], sc[i][j][3]);
      }
    }
    __syncthreads();

    // ---- online softmax: 4 threads per row (16 cols each) ----
    {
      const int row = t >> 2, part = t & 3;
      float4* pr = (float4*)&p_s[row * LP + part * 16];
      float4 v0 = pr[0], v1 = pr[1], v2 = pr[2], v3 = pr[3];
      float mt = fmaxf(fmaxf(fmaxf(v0.x, v0.y), fmaxf(v0.z, v0.w)),
                       fmaxf(fmaxf(v1.x, v1.y), fmaxf(v1.z, v1.w)));
      mt = fmaxf(mt, fmaxf(fmaxf(fmaxf(v2.x, v2.y), fmaxf(v2.z, v2.w)),
                           fmaxf(fmaxf(v3.x, v3.y), fmaxf(v3.z, v3.w))));
      mt = fmaxf(mt, __shfl_xor_sync(0xffffffffu, mt, 1));
      mt = fmaxf(mt, __shfl_xor_sync(0xffffffffu, mt, 2));
      float m_old = m_s[row];
      float mn = fmaxf(m_old, mt);
      v0.x = __expf(v0.x - mn); v0.y = __expf(v0.y - mn);
      v0.z = __expf(v0.z - mn); v0.w = __expf(v0.w - mn);
      v1.x = __expf(v1.x - mn); v1.y = __expf(v1.y - mn);
      v1.z = __expf(v1.z - mn); v1.w = __expf(v1.w - mn);
      v2.x = __expf(v2.x - mn); v2.y = __expf(v2.y - mn);
      v2.z = __expf(v2.z - mn); v2.w = __expf(v2.w - mn);
      v3.x = __expf(v3.x - mn); v3.y = __expf(v3.y - mn);
      v3.z = __expf(v3.z - mn); v3.w = __expf(v3.w - mn);
      float s = (v0.x + v0.y + v0.z + v0.w) + (v1.x + v1.y + v1.z + v1.w) +
                (v2.x + v2.y + v2.z + v2.w) + (v3.x + v3.y + v3.z + v3.w);
      s += __shfl_xor_sync(0xffffffffu, s, 1);
      s += __shfl_xor_sync(0xffffffffu, s, 2);
      pr[0] = tf32x4(v0); pr[1] = tf32x4(v1);
      pr[2] = tf32x4(v2); pr[3] = tf32x4(v3);
      __syncwarp();
      if (part == 0) {
        float alpha = __expf(m_old - mn);
        m_s[row] = mn;
        alpha_s[row] = alpha;
        l_s[row] = l_s[row] * alpha + s;
      }
    }
    __syncthreads();

    // ---- rescale O ----
#pragma unroll
    for (int i = 0; i < 2; i++) {
      int rA = wr * 32 + i * 16 + g;
      float aA = alpha_s[rA], aB = alpha_s[rA + 8];
#pragma unroll
      for (int j = 0; j < 4; j++) {
        o[i][j][0] *= aA; o[i][j][1] *= aA;
        o[i][j][2] *= aB; o[i][j][3] *= aB;
      }
    }

    // ---- phase B: O += P V (128x128), warp tile 32x32 ----
    const uint32_t* ps = (const uint32_t*)p_s;
    const uint32_t* vs = (const uint32_t*)v_s;
#pragma unroll
    for (int kk = 0; kk < KTT; kk += 8) {
      uint32_t af[2][4], bf[4][2];
#pragma unroll
      for (int i = 0; i < 2; i++) {
        int r0 = wr * 32 + i * 16;
        af[i][0] = ps[(r0 + g) * LP + kk + tg];
        af[i][1] = ps[(r0 + g + 8) * LP + kk + tg];
        af[i][2] = ps[(r0 + g) * LP + kk + tg + 4];
        af[i][3] = ps[(r0 + g + 8) * LP + kk + tg + 4];
      }
#pragma unroll
      for (int j = 0; j < 4; j++) {
        int cb = wc * 32 + j * 8;
        bf[j][0] = vs[(kk + tg) * LV + cb + g];
        bf[j][1] = vs[(kk + tg + 4) * LV + cb + g];
      }
#pragma unroll
      for (int i = 0; i < 2; i++)
#pragma unroll
        for (int j = 0; j < 4; j++) mma_tf32(o[i][j], af[i], bf[j]);
    }
  }

  // ---- epilogue: normalize + residual ----
#pragma unroll
  for (int i = 0; i < 2; i++) {
    int rA = wr * 32 + i * 16 + g;
    int rB = rA + 8;
    float invA = 1.f / l_s[rA];
    float invB = 1.f / l_s[rB];
#pragma unroll
    for (int j = 0; j < 4; j++) {
      int c = wc * 32 + j * 8 + 2 * tg;
      size_t baseA = ((size_t)b * S_ + q0 + rA) * D_ + (size_t)h * E_ + c;
      size_t baseB = ((size_t)b * S_ + q0 + rB) * D_ + (size_t)h * E_ + c;
      float2 mA = *(const float2*)(modin + baseA);
      float2 mB = *(const float2*)(modin + baseB);
      float2 oA = make_float2(mA.x + o[i][j][0] * invA, mA.y + o[i][j][1] * invA);
      float2 oB = make_float2(mB.x + o[i][j][2] * invB, mB.y + o[i][j][3] * invB);
      *(float2*)(modout + baseA) = oA;
      *(float2*)(modout + baseB) = oB;
    }
  }
}

// ============================================================
extern "C" void kernel_launch(void* const* d_in, const int* in_sizes, int n_in,
                              void* d_out, int out_size) {
  const float* x     = (const float*)d_in[0];
  const float* W_in  = (const float*)d_in[1];
  const float* gamma = (const float*)d_in[2];
  const float* beta  = (const float*)d_in[3];
  const float* Wq    = (const float*)d_in[4];
  const float* Wk    = (const float*)d_in[5];
  const float* Wv    = (const float*)d_in[6];
  const float* Wf    = (const float*)d_in[7];
  const float* bf    = (const float*)d_in[8];
  float* out = (float*)d_out;

  float *mod, *h, *q, *k, *v, *mod2, *h2;
  cudaGetSymbolAddress((void**)&mod,  g_mod);
  cudaGetSymbolAddress((void**)&h,    g_h);
  cudaGetSymbolAddress((void**)&q,    g_q);
  cudaGetSymbolAddress((void**)&k,    g_k);
  cudaGetSymbolAddress((void**)&v,    g_v);
  cudaGetSymbolAddress((void**)&mod2, g_mod2);
  cudaGetSymbolAddress((void**)&h2,   g_h2);

  cudaFuncSetAttribute(k_attn, cudaFuncAttributeMaxDynamicSharedMemorySize, ATTN_SMEM);

  dim3 gdense(D_ / GBN, NT_ / GBM);     // (8, 64)
  k_gemm_dense<<<gdense, 256>>>(x, W_in, mod);

  k_ln<<<NT_, 256>>>(mod, h, gamma, beta);

  dim3 gqkv(S_ / GBM, B_ * H_, 3);      // (16, 32, 3)
  k_gemm_qkv<<<gqkv, 256>>>(h, Wq, Wk, Wv, q, k, v);

  dim3 gattn(S_ / QT, H_, B_);          // (16, 8, 4)
  k_attn<<<gattn, 512, ATTN_SMEM>>>(q, k, v, mod, mod2);

  k_ln<<<NT_, 256>>>(mod2, h2, gamma, beta);

  k_gemm_ffn<<<gdense, 256>>>(h2, Wf, bf, mod2, out);
}

// round 10
// speedup vs baseline: 1.1482x; 1.1482x over previous
#include <cuda_runtime.h>
#include <math.h>
#include <stdint.h>

// ---------------- problem constants ----------------
#define D_   1024
#define H_   8
#define E_   128
#define B_   4
#define S_   2048
#define NT_  (B_ * S_)
#define EPS_ 1e-6f

// ---------------- device scratch ----------------
__device__ float g_mod [NT_ * D_];
__device__ float g_h   [NT_ * D_];
__device__ float g_q   [NT_ * D_];
__device__ float g_k   [NT_ * D_];
__device__ float g_v   [NT_ * D_];
__device__ float g_mod2[NT_ * D_];
__device__ float g_h2  [NT_ * D_];

__device__ __forceinline__ float elu1(float x) { return x > 0.f ? x : expm1f(x); }

__device__ __forceinline__ float f2tf(float f) {
  uint32_t u;
  asm("cvt.rna.tf32.f32 %0, %1;" : "=r"(u) : "f"(f));
  return __uint_as_float(u);
}
__device__ __forceinline__ uint32_t tf32bits(float f) {
  uint32_t u;
  asm("cvt.rna.tf32.f32 %0, %1;" : "=r"(u) : "f"(f));
  return u;
}
__device__ __forceinline__ float4 tf32x4(float4 v) {
  return make_float4(f2tf(v.x), f2tf(v.y), f2tf(v.z), f2tf(v.w));
}

__device__ __forceinline__ void mma_tf32(float* d, const uint32_t* a, const uint32_t* b) {
  asm volatile(
      "mma.sync.aligned.m16n8k8.row.col.f32.tf32.tf32.f32 "
      "{%0,%1,%2,%3}, {%4,%5,%6,%7}, {%8,%9}, {%0,%1,%2,%3};"
      : "+f"(d[0]), "+f"(d[1]), "+f"(d[2]), "+f"(d[3])
      : "r"(a[0]), "r"(a[1]), "r"(a[2]), "r"(a[3]), "r"(b[0]), "r"(b[1]));
}

// ============================================================
// TF32 tensor-core GEMM (R2/R7 core): 128x128 block tile, K-tile 32.
// 256 threads = 8 warps (2 x 4), warp tile 64x32.
// ============================================================
#define GBM 128
#define GBN 128
#define GBK 32
#define LDA_S 36
#define LDB_S 136

template <bool FFN>
__device__ __forceinline__ void gemm_tf32_core(
    const float* __restrict__ A, int lda,
    const float* __restrict__ Bm, int ldb,
    float* __restrict__ C, int ldc, int K,
    const float* __restrict__ bias, const float* __restrict__ resid) {
  __shared__ float As[GBM * LDA_S];
  __shared__ float Bs[GBK * LDB_S];

  const int t = threadIdx.x;
  const int lane = t & 31, wid = t >> 5;
  const int g = lane >> 2, tg = lane & 3;
  const int wr = wid >> 2, wc = wid & 3;

  const int a_c = (t & 7) * 4;
  const int a_r = t >> 3;
  const int b_c = (t & 31) * 4;
  const int b_r = t >> 5;

  float acc[4][4][4];
#pragma unroll
  for (int i = 0; i < 4; i++)
#pragma unroll
    for (int j = 0; j < 4; j++)
#pragma unroll
      for (int r = 0; r < 4; r++) acc[i][j][r] = 0.f;

  for (int k0 = 0; k0 < K; k0 += GBK) {
#pragma unroll
    for (int i = 0; i < 4; i++) {
      int r = a_r + i * 32;
      float4 v = *(const float4*)(A + (size_t)r * lda + k0 + a_c);
      *(float4*)&As[r * LDA_S + a_c] = tf32x4(v);
    }
#pragma unroll
    for (int i = 0; i < 4; i++) {
      int r = b_r + i * 8;
      float4 v = *(const float4*)(Bm + (size_t)(k0 + r) * ldb + b_c);
      *(float4*)&Bs[r * LDB_S + b_c] = tf32x4(v);
    }
    __syncthreads();

    const uint32_t* as = (const uint32_t*)As;
    const uint32_t* bs = (const uint32_t*)Bs;
#pragma unroll
    for (int kk = 0; kk < GBK; kk += 8) {
      uint32_t af[4][4], bf[4][2];
#pragma unroll
      for (int i = 0; i < 4; i++) {
        int r0 = wr * 64 + i * 16;
        af[i][0] = as[(r0 + g) * LDA_S + kk + tg];
        af[i][1] = as[(r0 + g + 8) * LDA_S + kk + tg];
        af[i][2] = as[(r0 + g) * LDA_S + kk + tg + 4];
        af[i][3] = as[(r0 + g + 8) * LDA_S + kk + tg + 4];
      }
#pragma unroll
      for (int j = 0; j < 4; j++) {
        int c0 = wc * 32 + j * 8;
        bf[j][0] = bs[(kk + tg) * LDB_S + c0 + g];
        bf[j][1] = bs[(kk + tg + 4) * LDB_S + c0 + g];
      }
#pragma unroll
      for (int i = 0; i < 4; i++)
#pragma unroll
        for (int j = 0; j < 4; j++) mma_tf32(acc[i][j], af[i], bf[j]);
    }
    __syncthreads();
  }

#pragma unroll
  for (int i = 0; i < 4; i++) {
    int rA = wr * 64 + i * 16 + g;
    int rB = rA + 8;
#pragma unroll
    for (int j = 0; j < 4; j++) {
      int c = wc * 32 + j * 8 + 2 * tg;
      float2 o0 = make_float2(acc[i][j][0], acc[i][j][1]);
      float2 o1 = make_float2(acc[i][j][2], acc[i][j][3]);
      if (FFN) {
        float2 bv = *(const float2*)(bias + c);
        float2 r0 = *(const float2*)(resid + (size_t)rA * ldc + c);
        float2 r1 = *(const float2*)(resid + (size_t)rB * ldc + c);
        o0.x = r0.x + elu1(o0.x + bv.x);
        o0.y = r0.y + elu1(o0.y + bv.y);
        o1.x = r1.x + elu1(o1.x + bv.x);
        o1.y = r1.y + elu1(o1.y + bv.y);
      }
      *(float2*)(C + (size_t)rA * ldc + c) = o0;
      *(float2*)(C + (size_t)rB * ldc + c) = o1;
    }
  }
}

__global__ void __launch_bounds__(256) k_gemm_dense(const float* __restrict__ A,
                                                    const float* __restrict__ W,
                                                    float* __restrict__ C) {
  const size_t moff = (size_t)blockIdx.y * GBM * D_;
  gemm_tf32_core<false>(A + moff, D_, W + blockIdx.x * GBN, D_,
                        C + moff + blockIdx.x * GBN, D_, D_, nullptr, nullptr);
}

__global__ void __launch_bounds__(256) k_gemm_ffn(const float* __restrict__ A,
                                                  const float* __restrict__ W,
                                                  const float* __restrict__ bias,
                                                  const float* __restrict__ resid,
                                                  float* __restrict__ C) {
  const size_t moff = (size_t)blockIdx.y * GBM * D_;
  const size_t off = moff + blockIdx.x * GBN;
  gemm_tf32_core<true>(A + moff, D_, W + blockIdx.x * GBN, D_, C + off, D_, D_,
                       bias + blockIdx.x * GBN, resid + off);
}

__global__ void __launch_bounds__(256) k_gemm_qkv(const float* __restrict__ Hm,
                                                  const float* __restrict__ Wq,
                                                  const float* __restrict__ Wk,
                                                  const float* __restrict__ Wv,
                                                  float* __restrict__ Oq,
                                                  float* __restrict__ Ok,
                                                  float* __restrict__ Ov) {
  const int which = blockIdx.z;
  const float* W = which == 0 ? Wq : (which == 1 ? Wk : Wv);
  float* Out = which == 0 ? Oq : (which == 1 ? Ok : Ov);
  const int bh = blockIdx.y;
  const int b = bh >> 3, h = bh & 7;
  const float* A = Hm + ((size_t)b * S_ + (size_t)blockIdx.x * GBM) * D_ + h * E_;
  const float* Wp = W + h * E_ * E_;
  float* C = Out + ((size_t)bh * S_ + (size_t)blockIdx.x * GBM) * E_;
  gemm_tf32_core<false>(A, D_, Wp, E_, C, E_, E_, nullptr, nullptr);
}

// ============================================================
// LayerNorm over last dim (1024), one block per row
// ============================================================
__global__ void __launch_bounds__(256) k_ln(const float* __restrict__ in,
                                            float* __restrict__ out,
                                            const float* __restrict__ gamma,
                                            const float* __restrict__ beta) {
  const size_t row = blockIdx.x;
  const int t = threadIdx.x;
  float4 v = ((const float4*)(in + row * D_))[t];
  float s  = v.x + v.y + v.z + v.w;
  float s2 = v.x * v.x + v.y * v.y + v.z * v.z + v.w * v.w;
#pragma unroll
  for (int off = 16; off; off >>= 1) {
    s  += __shfl_xor_sync(0xffffffffu, s, off);
    s2 += __shfl_xor_sync(0xffffffffu, s2, off);
  }
  __shared__ float sb[16];
  if ((t & 31) == 0) { sb[t >> 5] = s; sb[(t >> 5) + 8] = s2; }
  __syncthreads();
  float tot = 0.f, tot2 = 0.f;
#pragma unroll
  for (int i = 0; i < 8; i++) { tot += sb[i]; tot2 += sb[i + 8]; }
  const float mean = tot * (1.f / D_);
  const float var  = tot2 * (1.f / D_) - mean * mean;
  const float inv  = rsqrtf(var + EPS_);
  float4 gm = ((const float4*)gamma)[t];
  float4 bb = ((const float4*)beta)[t];
  float4 o;
  o.x = (v.x - mean) * inv * gm.x + bb.x;
  o.y = (v.y - mean) * inv * gm.y + bb.y;
  o.z = (v.z - mean) * inv * gm.z + bb.z;
  o.w = (v.w - mean) * inv * gm.w + bb.w;
  ((float4*)(out + row * D_))[t] = o;
}

// ============================================================
// Flash attention v2-style: QT=128, KT=64, 8 warps, each warp
// owns 16 full query rows. Q in registers; softmax fully in
// registers (quad shuffles); P through warp-private smem with
// __syncwarp only. 2 block barriers per KV tile.
// ============================================================
#define QT 128
#define KTT 64
#define NKT (S_ / KTT)
#define LK 132
#define LV 136
#define LP 68
#define ATTN_SMEM ((64 * LK + 64 * LV + QT * LP) * 4)

__global__ void __launch_bounds__(256) k_attn(const float* __restrict__ Qg,
                                              const float* __restrict__ Kg,
                                              const float* __restrict__ Vg,
                                              const float* __restrict__ modin,
                                              float* __restrict__ modout) {
  extern __shared__ float sm[];
  float* k_s = sm;                          // [64][LK]
  float* v_s = sm + 64 * LK;                // [64][LV]
  float* p_s = sm + 64 * LK + 64 * LV;      // [128][LP], warp-private rows

  const int t = threadIdx.x;
  const int lane = t & 31, w = t >> 5;
  const int g = lane >> 2, tg = lane & 3;
  const int row0 = w * 16;                  // warp's query-row block

  const int q0 = blockIdx.x * QT;
  const int h = blockIdx.y, b = blockIdx.z;
  const size_t bh = (size_t)b * H_ + h;

  const float* Kp = Kg + bh * S_ * E_;
  const float* Vp = Vg + bh * S_ * E_;

  const int ldrow = t >> 5, ldcol = (t & 31) * 4;

  // ---- stage Q (tf32) into smem scratch (k_s/v_s region), then to regs ----
  {
    const float* Qp = Qg + (bh * S_ + q0) * E_;
#pragma unroll
    for (int i = 0; i < 16; i++) {
      int r = ldrow + i * 8;
      float4 v = *(const float4*)(Qp + (size_t)r * E_ + ldcol);
      *(float4*)&sm[r * 132 + ldcol] = tf32x4(v);
    }
  }
  __syncthreads();

  uint32_t qf[16][4];
  {
    const uint32_t* qs = (const uint32_t*)sm;
#pragma unroll
    for (int kk = 0; kk < 16; kk++) {
      qf[kk][0] = qs[(row0 + g) * 132 + kk * 8 + tg];
      qf[kk][1] = qs[(row0 + g + 8) * 132 + kk * 8 + tg];
      qf[kk][2] = qs[(row0 + g) * 132 + kk * 8 + tg + 4];
      qf[kk][3] = qs[(row0 + g + 8) * 132 + kk * 8 + tg + 4];
    }
  }
  __syncthreads();

  float o[16][4];
#pragma unroll
  for (int j = 0; j < 16; j++)
#pragma unroll
    for (int r = 0; r < 4; r++) o[j][r] = 0.f;

  float mA = -1e30f, mB = -1e30f, lA = 0.f, lB = 0.f;

  for (int kt = 0; kt < NKT; kt++) {
    if (kt) __syncthreads();   // protect K/V overwrite
    {
      const float* kb = Kp + (size_t)kt * KTT * E_;
      const float* vb = Vp + (size_t)kt * KTT * E_;
#pragma unroll
      for (int i = 0; i < 8; i++) {
        int r = ldrow + i * 8;
        float4 kv = *(const float4*)(kb + (size_t)r * E_ + ldcol);
        float4 vv = *(const float4*)(vb + (size_t)r * E_ + ldcol);
        *(float4*)&k_s[r * LK + ldcol] = tf32x4(kv);
        *(float4*)&v_s[r * LV + ldcol] = tf32x4(vv);
      }
    }
    __syncthreads();

    // ---- phase A: scores (16 x 64) = Q K^T, all in this warp ----
    float sc[8][4];
#pragma unroll
    for (int j = 0; j < 8; j++)
#pragma unroll
      for (int r = 0; r < 4; r++) sc[j][r] = 0.f;

    const uint32_t* ks = (const uint32_t*)k_s;
#pragma unroll
    for (int kk = 0; kk < 16; kk++) {
      uint32_t bf[8][2];
#pragma unroll
      for (int j = 0; j < 8; j++) {
        bf[j][0] = ks[(j * 8 + g) * LK + kk * 8 + tg];
        bf[j][1] = ks[(j * 8 + g) * LK + kk * 8 + tg + 4];
      }
#pragma unroll
      for (int j = 0; j < 8; j++) mma_tf32(sc[j], qf[kk], bf[j]);
    }

    // ---- register softmax (rows g and g+8 of this warp's block) ----
    {
      float mtA = -1e30f, mtB = -1e30f;
#pragma unroll
      for (int j = 0; j < 8; j++) {
        mtA = fmaxf(mtA, fmaxf(sc[j][0], sc[j][1]));
        mtB = fmaxf(mtB, fmaxf(sc[j][2], sc[j][3]));
      }
      mtA = fmaxf(mtA, __shfl_xor_sync(0xffffffffu, mtA, 1));
      mtA = fmaxf(mtA, __shfl_xor_sync(0xffffffffu, mtA, 2));
      mtB = fmaxf(mtB, __shfl_xor_sync(0xffffffffu, mtB, 1));
      mtB = fmaxf(mtB, __shfl_xor_sync(0xffffffffu, mtB, 2));
      float mnA = fmaxf(mA, mtA), mnB = fmaxf(mB, mtB);
      float aA = __expf(mA - mnA), aB = __expf(mB - mnB);
      mA = mnA; mB = mnB;
      float sA = 0.f, sB = 0.f;
#pragma unroll
      for (int j = 0; j < 8; j++) {
        sc[j][0] = __expf(sc[j][0] - mnA);
        sc[j][1] = __expf(sc[j][1] - mnA);
        sc[j][2] = __expf(sc[j][2] - mnB);
        sc[j][3] = __expf(sc[j][3] - mnB);
        sA += sc[j][0] + sc[j][1];
        sB += sc[j][2] + sc[j][3];
      }
      sA += __shfl_xor_sync(0xffffffffu, sA, 1);
      sA += __shfl_xor_sync(0xffffffffu, sA, 2);
      sB += __shfl_xor_sync(0xffffffffu, sB, 1);
      sB += __shfl_xor_sync(0xffffffffu, sB, 2);
      lA = lA * aA + sA;
      lB = lB * aB + sB;
      // rescale O
#pragma unroll
      for (int j = 0; j < 16; j++) {
        o[j][0] *= aA; o[j][1] *= aA;
        o[j][2] *= aB; o[j][3] *= aB;
      }
    }

    // ---- write P (tf32) to warp-private smem rows ----
#pragma unroll
    for (int j = 0; j < 8; j++) {
      int c = j * 8 + 2 * tg;
      uint32_t* pA = (uint32_t*)&p_s[(row0 + g) * LP + c];
      uint32_t* pB = (uint32_t*)&p_s[(row0 + g + 8) * LP + c];
      pA[0] = tf32bits(sc[j][0]); pA[1] = tf32bits(sc[j][1]);
      pB[0] = tf32bits(sc[j][2]); pB[1] = tf32bits(sc[j][3]);
    }
    __syncwarp();

    // ---- phase B: O (16 x 128) += P V ----
    const uint32_t* ps = (const uint32_t*)p_s;
    const uint32_t* vs = (const uint32_t*)v_s;
#pragma unroll
    for (int kk = 0; kk < 8; kk++) {
      uint32_t af[4];
      af[0] = ps[(row0 + g) * LP + kk * 8 + tg];
      af[1] = ps[(row0 + g + 8) * LP + kk * 8 + tg];
      af[2] = ps[(row0 + g) * LP + kk * 8 + tg + 4];
      af[3] = ps[(row0 + g + 8) * LP + kk * 8 + tg + 4];
      uint32_t bf[16][2];
#pragma unroll
      for (int j = 0; j < 16; j++) {
        bf[j][0] = vs[(kk * 8 + tg) * LV + j * 8 + g];
        bf[j][1] = vs[(kk * 8 + tg + 4) * LV + j * 8 + g];
      }
#pragma unroll
      for (int j = 0; j < 16; j++) mma_tf32(o[j], af, bf[j]);
    }
  }

  // ---- epilogue: normalize + residual ----
  {
    float invA = 1.f / lA, invB = 1.f / lB;
    const int rA = q0 + row0 + g, rB = rA + 8;
#pragma unroll
    for (int j = 0; j < 16; j++) {
      int c = j * 8 + 2 * tg;
      size_t baseA = ((size_t)b * S_ + rA) * D_ + (size_t)h * E_ + c;
      size_t baseB = ((size_t)b * S_ + rB) * D_ + (size_t)h * E_ + c;
      float2 mAv = *(const float2*)(modin + baseA);
      float2 mBv = *(const float2*)(modin + baseB);
      float2 oA = make_float2(mAv.x + o[j][0] * invA, mAv.y + o[j][1] * invA);
      float2 oB = make_float2(mBv.x + o[j][2] * invB, mBv.y + o[j][3] * invB);
      *(float2*)(modout + baseA) = oA;
      *(float2*)(modout + baseB) = oB;
    }
  }
}

// ============================================================
extern "C" void kernel_launch(void* const* d_in, const int* in_sizes, int n_in,
                              void* d_out, int out_size) {
  const float* x     = (const float*)d_in[0];
  const float* W_in  = (const float*)d_in[1];
  const float* gamma = (const float*)d_in[2];
  const float* beta  = (const float*)d_in[3];
  const float* Wq    = (const float*)d_in[4];
  const float* Wk    = (const float*)d_in[5];
  const float* Wv    = (const float*)d_in[6];
  const float* Wf    = (const float*)d_in[7];
  const float* bf    = (const float*)d_in[8];
  float* out = (float*)d_out;

  float *mod, *h, *q, *k, *v, *mod2, *h2;
  cudaGetSymbolAddress((void**)&mod,  g_mod);
  cudaGetSymbolAddress((void**)&h,    g_h);
  cudaGetSymbolAddress((void**)&q,    g_q);
  cudaGetSymbolAddress((void**)&k,    g_k);
  cudaGetSymbolAddress((void**)&v,    g_v);
  cudaGetSymbolAddress((void**)&mod2, g_mod2);
  cudaGetSymbolAddress((void**)&h2,   g_h2);

  cudaFuncSetAttribute(k_attn, cudaFuncAttributeMaxDynamicSharedMemorySize, ATTN_SMEM);

  dim3 gdense(D_ / GBN, NT_ / GBM);     // (8, 64)
  k_gemm_dense<<<gdense, 256>>>(x, W_in, mod);

  k_ln<<<NT_, 256>>>(mod, h, gamma, beta);

  dim3 gqkv(S_ / GBM, B_ * H_, 3);      // (16, 32, 3)
  k_gemm_qkv<<<gqkv, 256>>>(h, Wq, Wk, Wv, q, k, v);

  dim3 gattn(S_ / QT, H_, B_);          // (16, 8, 4)
  k_attn<<<gattn, 256, ATTN_SMEM>>>(q, k, v, mod, mod2);

  k_ln<<<NT_, 256>>>(mod2, h2, gamma, beta);

  k_gemm_ffn<<<gdense, 256>>>(h2, Wf, bf, mod2, out);
}

// round 11
// speedup vs baseline: 1.2118x; 1.0554x over previous
#include <cuda_runtime.h>
#include <math.h>
#include <stdint.h>

// ---------------- problem constants ----------------
#define D_   1024
#define H_   8
#define E_   128
#define B_   4
#define S_   2048
#define NT_  (B_ * S_)
#define EPS_ 1e-6f

// ---------------- device scratch ----------------
__device__ float g_mod [NT_ * D_];
__device__ float g_h   [NT_ * D_];
__device__ float g_q   [NT_ * D_];
__device__ float g_k   [NT_ * D_];
__device__ float g_v   [NT_ * D_];
__device__ float g_mod2[NT_ * D_];
__device__ float g_h2  [NT_ * D_];

__device__ __forceinline__ float elu1(float x) { return x > 0.f ? x : expm1f(x); }

__device__ __forceinline__ float f2tf(float f) {
  uint32_t u;
  asm("cvt.rna.tf32.f32 %0, %1;" : "=r"(u) : "f"(f));
  return __uint_as_float(u);
}
__device__ __forceinline__ uint32_t tf32bits(float f) {
  uint32_t u;
  asm("cvt.rna.tf32.f32 %0, %1;" : "=r"(u) : "f"(f));
  return u;
}
__device__ __forceinline__ float4 tf32x4(float4 v) {
  return make_float4(f2tf(v.x), f2tf(v.y), f2tf(v.z), f2tf(v.w));
}

__device__ __forceinline__ void mma_tf32(float* d, const uint32_t* a, const uint32_t* b) {
  asm volatile(
      "mma.sync.aligned.m16n8k8.row.col.f32.tf32.tf32.f32 "
      "{%0,%1,%2,%3}, {%4,%5,%6,%7}, {%8,%9}, {%0,%1,%2,%3};"
      : "+f"(d[0]), "+f"(d[1]), "+f"(d[2]), "+f"(d[3])
      : "r"(a[0]), "r"(a[1]), "r"(a[2]), "r"(a[3]), "r"(b[0]), "r"(b[1]));
}

__device__ __forceinline__ void cp16(float* s, const float* g) {
  uint32_t sa = (uint32_t)__cvta_generic_to_shared(s);
  asm volatile("cp.async.cg.shared.global [%0], [%1], 16;" :: "r"(sa), "l"(g));
}
#define CP_COMMIT() asm volatile("cp.async.commit_group;")
#define CP_WAIT0()  asm volatile("cp.async.wait_group 0;")

// ============================================================
// TF32 tensor-core GEMM (R2/R7 core): 128x128 block tile, K-tile 32.
// 256 threads = 8 warps (2 x 4), warp tile 64x32.
// ============================================================
#define GBM 128
#define GBN 128
#define GBK 32
#define LDA_S 36
#define LDB_S 136

template <bool FFN>
__device__ __forceinline__ void gemm_tf32_core(
    const float* __restrict__ A, int lda,
    const float* __restrict__ Bm, int ldb,
    float* __restrict__ C, int ldc, int K,
    const float* __restrict__ bias, const float* __restrict__ resid) {
  __shared__ float As[GBM * LDA_S];
  __shared__ float Bs[GBK * LDB_S];

  const int t = threadIdx.x;
  const int lane = t & 31, wid = t >> 5;
  const int g = lane >> 2, tg = lane & 3;
  const int wr = wid >> 2, wc = wid & 3;

  const int a_c = (t & 7) * 4;
  const int a_r = t >> 3;
  const int b_c = (t & 31) * 4;
  const int b_r = t >> 5;

  float acc[4][4][4];
#pragma unroll
  for (int i = 0; i < 4; i++)
#pragma unroll
    for (int j = 0; j < 4; j++)
#pragma unroll
      for (int r = 0; r < 4; r++) acc[i][j][r] = 0.f;

  for (int k0 = 0; k0 < K; k0 += GBK) {
#pragma unroll
    for (int i = 0; i < 4; i++) {
      int r = a_r + i * 32;
      float4 v = *(const float4*)(A + (size_t)r * lda + k0 + a_c);
      *(float4*)&As[r * LDA_S + a_c] = tf32x4(v);
    }
#pragma unroll
    for (int i = 0; i < 4; i++) {
      int r = b_r + i * 8;
      float4 v = *(const float4*)(Bm + (size_t)(k0 + r) * ldb + b_c);
      *(float4*)&Bs[r * LDB_S + b_c] = tf32x4(v);
    }
    __syncthreads();

    const uint32_t* as = (const uint32_t*)As;
    const uint32_t* bs = (const uint32_t*)Bs;
#pragma unroll
    for (int kk = 0; kk < GBK; kk += 8) {
      uint32_t af[4][4], bf[4][2];
#pragma unroll
      for (int i = 0; i < 4; i++) {
        int r0 = wr * 64 + i * 16;
        af[i][0] = as[(r0 + g) * LDA_S + kk + tg];
        af[i][1] = as[(r0 + g + 8) * LDA_S + kk + tg];
        af[i][2] = as[(r0 + g) * LDA_S + kk + tg + 4];
        af[i][3] = as[(r0 + g + 8) * LDA_S + kk + tg + 4];
      }
#pragma unroll
      for (int j = 0; j < 4; j++) {
        int c0 = wc * 32 + j * 8;
        bf[j][0] = bs[(kk + tg) * LDB_S + c0 + g];
        bf[j][1] = bs[(kk + tg + 4) * LDB_S + c0 + g];
      }
#pragma unroll
      for (int i = 0; i < 4; i++)
#pragma unroll
        for (int j = 0; j < 4; j++) mma_tf32(acc[i][j], af[i], bf[j]);
    }
    __syncthreads();
  }

#pragma unroll
  for (int i = 0; i < 4; i++) {
    int rA = wr * 64 + i * 16 + g;
    int rB = rA + 8;
#pragma unroll
    for (int j = 0; j < 4; j++) {
      int c = wc * 32 + j * 8 + 2 * tg;
      float2 o0 = make_float2(acc[i][j][0], acc[i][j][1]);
      float2 o1 = make_float2(acc[i][j][2], acc[i][j][3]);
      if (FFN) {
        float2 bv = *(const float2*)(bias + c);
        float2 r0 = *(const float2*)(resid + (size_t)rA * ldc + c);
        float2 r1 = *(const float2*)(resid + (size_t)rB * ldc + c);
        o0.x = r0.x + elu1(o0.x + bv.x);
        o0.y = r0.y + elu1(o0.y + bv.y);
        o1.x = r1.x + elu1(o1.x + bv.x);
        o1.y = r1.y + elu1(o1.y + bv.y);
      }
      *(float2*)(C + (size_t)rA * ldc + c) = o0;
      *(float2*)(C + (size_t)rB * ldc + c) = o1;
    }
  }
}

__global__ void __launch_bounds__(256) k_gemm_dense(const float* __restrict__ A,
                                                    const float* __restrict__ W,
                                                    float* __restrict__ C) {
  const size_t moff = (size_t)blockIdx.y * GBM * D_;
  gemm_tf32_core<false>(A + moff, D_, W + blockIdx.x * GBN, D_,
                        C + moff + blockIdx.x * GBN, D_, D_, nullptr, nullptr);
}

__global__ void __launch_bounds__(256) k_gemm_ffn(const float* __restrict__ A,
                                                  const float* __restrict__ W,
                                                  const float* __restrict__ bias,
                                                  const float* __restrict__ resid,
                                                  float* __restrict__ C) {
  const size_t moff = (size_t)blockIdx.y * GBM * D_;
  const size_t off = moff + blockIdx.x * GBN;
  gemm_tf32_core<true>(A + moff, D_, W + blockIdx.x * GBN, D_, C + off, D_, D_,
                       bias + blockIdx.x * GBN, resid + off);
}

__global__ void __launch_bounds__(256) k_gemm_qkv(const float* __restrict__ Hm,
                                                  const float* __restrict__ Wq,
                                                  const float* __restrict__ Wk,
                                                  const float* __restrict__ Wv,
                                                  float* __restrict__ Oq,
                                                  float* __restrict__ Ok,
                                                  float* __restrict__ Ov) {
  const int which = blockIdx.z;
  const float* W = which == 0 ? Wq : (which == 1 ? Wk : Wv);
  float* Out = which == 0 ? Oq : (which == 1 ? Ok : Ov);
  const int bh = blockIdx.y;
  const int b = bh >> 3, h = bh & 7;
  const float* A = Hm + ((size_t)b * S_ + (size_t)blockIdx.x * GBM) * D_ + h * E_;
  const float* Wp = W + h * E_ * E_;
  float* C = Out + ((size_t)bh * S_ + (size_t)blockIdx.x * GBM) * E_;
  gemm_tf32_core<false>(A, D_, Wp, E_, C, E_, E_, nullptr, nullptr);
}

// ============================================================
// LayerNorm over last dim (1024), one block per row
// ============================================================
__global__ void __launch_bounds__(256) k_ln(const float* __restrict__ in,
                                            float* __restrict__ out,
                                            const float* __restrict__ gamma,
                                            const float* __restrict__ beta) {
  const size_t row = blockIdx.x;
  const int t = threadIdx.x;
  float4 v = ((const float4*)(in + row * D_))[t];
  float s  = v.x + v.y + v.z + v.w;
  float s2 = v.x * v.x + v.y * v.y + v.z * v.z + v.w * v.w;
#pragma unroll
  for (int off = 16; off; off >>= 1) {
    s  += __shfl_xor_sync(0xffffffffu, s, off);
    s2 += __shfl_xor_sync(0xffffffffu, s2, off);
  }
  __shared__ float sb[16];
  if ((t & 31) == 0) { sb[t >> 5] = s; sb[(t >> 5) + 8] = s2; }
  __syncthreads();
  float tot = 0.f, tot2 = 0.f;
#pragma unroll
  for (int i = 0; i < 8; i++) { tot += sb[i]; tot2 += sb[i + 8]; }
  const float mean = tot * (1.f / D_);
  const float var  = tot2 * (1.f / D_) - mean * mean;
  const float inv  = rsqrtf(var + EPS_);
  float4 gm = ((const float4*)gamma)[t];
  float4 bb = ((const float4*)beta)[t];
  float4 o;
  o.x = (v.x - mean) * inv * gm.x + bb.x;
  o.y = (v.y - mean) * inv * gm.y + bb.y;
  o.z = (v.z - mean) * inv * gm.z + bb.z;
  o.w = (v.w - mean) * inv * gm.w + bb.w;
  ((float4*)(out + row * D_))[t] = o;
}

// ============================================================
// Flash attention v2-style + cp.async double-buffered K/V.
// QT=128, KT=64, 8 warps, each warp owns 16 full query rows.
// K/V stored as RAW fp32 (mma truncates to tf32); Q and P use
// cvt.rna. Register softmax; P via warp-private smem rows.
// ONE block barrier per KV tile.
// ============================================================
#define QT 128
#define KTT 64
#define NKT (S_ / KTT)
#define LK 132
#define LV 136
#define LP 68
#define ATTN_SMEM ((2 * 64 * LK + 2 * 64 * LV + QT * LP) * 4)

__global__ void __launch_bounds__(256) k_attn(const float* __restrict__ Qg,
                                              const float* __restrict__ Kg,
                                              const float* __restrict__ Vg,
                                              const float* __restrict__ modin,
                                              float* __restrict__ modout) {
  extern __shared__ float sm[];
  float* k_s = sm;                          // [2][64][LK]
  float* v_s = sm + 2 * 64 * LK;            // [2][64][LV]
  float* p_s = sm + 2 * 64 * LK + 2 * 64 * LV;  // [128][LP]

  const int t = threadIdx.x;
  const int lane = t & 31, w = t >> 5;
  const int g = lane >> 2, tg = lane & 3;
  const int row0 = w * 16;

  const int q0 = blockIdx.x * QT;
  const int h = blockIdx.y, b = blockIdx.z;
  const size_t bh = (size_t)b * H_ + h;

  const float* Kp = Kg + bh * S_ * E_;
  const float* Vp = Vg + bh * S_ * E_;

  const int ldrow = t >> 5, ldcol = (t & 31) * 4;

  // ---- stage Q (tf32, RNA) via smem scratch, then into registers ----
  {
    const float* Qp = Qg + (bh * S_ + q0) * E_;
#pragma unroll
    for (int i = 0; i < 16; i++) {
      int r = ldrow + i * 8;
      float4 v = *(const float4*)(Qp + (size_t)r * E_ + ldcol);
      *(float4*)&sm[r * 132 + ldcol] = tf32x4(v);
    }
  }
  __syncthreads();

  uint32_t qf[16][4];
  {
    const uint32_t* qs = (const uint32_t*)sm;
#pragma unroll
    for (int kk = 0; kk < 16; kk++) {
      qf[kk][0] = qs[(row0 + g) * 132 + kk * 8 + tg];
      qf[kk][1] = qs[(row0 + g + 8) * 132 + kk * 8 + tg];
      qf[kk][2] = qs[(row0 + g) * 132 + kk * 8 + tg + 4];
      qf[kk][3] = qs[(row0 + g + 8) * 132 + kk * 8 + tg + 4];
    }
  }
  __syncthreads();

  // ---- cp.async K/V loader (raw fp32, no conversion) ----
  auto load_kv = [&](int st, int kt) {
    float* ks = k_s + st * 64 * LK;
    float* vs = v_s + st * 64 * LV;
    const float* kb = Kp + (size_t)kt * KTT * E_;
    const float* vb = Vp + (size_t)kt * KTT * E_;
#pragma unroll
    for (int i = 0; i < 8; i++) {
      int r = ldrow + i * 8;
      cp16(&ks[r * LK + ldcol], kb + (size_t)r * E_ + ldcol);
      cp16(&vs[r * LV + ldcol], vb + (size_t)r * E_ + ldcol);
    }
  };

  load_kv(0, 0);
  CP_COMMIT();

  float o[16][4];
#pragma unroll
  for (int j = 0; j < 16; j++)
#pragma unroll
    for (int r = 0; r < 4; r++) o[j][r] = 0.f;

  float mA = -1e30f, mB = -1e30f, lA = 0.f, lB = 0.f;

  for (int kt = 0; kt < NKT; kt++) {
    const int cur = kt & 1;
    CP_WAIT0();
    __syncthreads();            // stage cur ready; prev iter's reads done
    if (kt + 1 < NKT) {
      load_kv(cur ^ 1, kt + 1);
      CP_COMMIT();
    }
    const uint32_t* ks = (const uint32_t*)(k_s + cur * 64 * LK);
    const uint32_t* vs = (const uint32_t*)(v_s + cur * 64 * LV);

    // ---- phase A: scores (16 x 64) = Q K^T ----
    float sc[8][4];
#pragma unroll
    for (int j = 0; j < 8; j++)
#pragma unroll
      for (int r = 0; r < 4; r++) sc[j][r] = 0.f;

#pragma unroll
    for (int kk = 0; kk < 16; kk++) {
      uint32_t bf[8][2];
#pragma unroll
      for (int j = 0; j < 8; j++) {
        bf[j][0] = ks[(j * 8 + g) * LK + kk * 8 + tg];
        bf[j][1] = ks[(j * 8 + g) * LK + kk * 8 + tg + 4];
      }
#pragma unroll
      for (int j = 0; j < 8; j++) mma_tf32(sc[j], qf[kk], bf[j]);
    }

    // ---- register softmax ----
    {
      float mtA = -1e30f, mtB = -1e30f;
#pragma unroll
      for (int j = 0; j < 8; j++) {
        mtA = fmaxf(mtA, fmaxf(sc[j][0], sc[j][1]));
        mtB = fmaxf(mtB, fmaxf(sc[j][2], sc[j][3]));
      }
      mtA = fmaxf(mtA, __shfl_xor_sync(0xffffffffu, mtA, 1));
      mtA = fmaxf(mtA, __shfl_xor_sync(0xffffffffu, mtA, 2));
      mtB = fmaxf(mtB, __shfl_xor_sync(0xffffffffu, mtB, 1));
      mtB = fmaxf(mtB, __shfl_xor_sync(0xffffffffu, mtB, 2));
      float mnA = fmaxf(mA, mtA), mnB = fmaxf(mB, mtB);
      float aA = __expf(mA - mnA), aB = __expf(mB - mnB);
      mA = mnA; mB = mnB;
      float sA = 0.f, sB = 0.f;
#pragma unroll
      for (int j = 0; j < 8; j++) {
        sc[j][0] = __expf(sc[j][0] - mnA);
        sc[j][1] = __expf(sc[j][1] - mnA);
        sc[j][2] = __expf(sc[j][2] - mnB);
        sc[j][3] = __expf(sc[j][3] - mnB);
        sA += sc[j][0] + sc[j][1];
        sB += sc[j][2] + sc[j][3];
      }
      sA += __shfl_xor_sync(0xffffffffu, sA, 1);
      sA += __shfl_xor_sync(0xffffffffu, sA, 2);
      sB += __shfl_xor_sync(0xffffffffu, sB, 1);
      sB += __shfl_xor_sync(0xffffffffu, sB, 2);
      lA = lA * aA + sA;
      lB = lB * aB + sB;
#pragma unroll
      for (int j = 0; j < 16; j++) {
        o[j][0] *= aA; o[j][1] *= aA;
        o[j][2] *= aB; o[j][3] *= aB;
      }
    }

    // ---- write P (tf32 RNA) to warp-private smem rows ----
#pragma unroll
    for (int j = 0; j < 8; j++) {
      int c = j * 8 + 2 * tg;
      uint32_t* pA = (uint32_t*)&p_s[(row0 + g) * LP + c];
      uint32_t* pB = (uint32_t*)&p_s[(row0 + g + 8) * LP + c];
      pA[0] = tf32bits(sc[j][0]); pA[1] = tf32bits(sc[j][1]);
      pB[0] = tf32bits(sc[j][2]); pB[1] = tf32bits(sc[j][3]);
    }
    __syncwarp();

    // ---- phase B: O (16 x 128) += P V ----
    const uint32_t* ps = (const uint32_t*)p_s;
#pragma unroll
    for (int kk = 0; kk < 8; kk++) {
      uint32_t af[4];
      af[0] = ps[(row0 + g) * LP + kk * 8 + tg];
      af[1] = ps[(row0 + g + 8) * LP + kk * 8 + tg];
      af[2] = ps[(row0 + g) * LP + kk * 8 + tg + 4];
      af[3] = ps[(row0 + g + 8) * LP + kk * 8 + tg + 4];
      uint32_t bf[16][2];
#pragma unroll
      for (int j = 0; j < 16; j++) {
        bf[j][0] = vs[(kk * 8 + tg) * LV + j * 8 + g];
        bf[j][1] = vs[(kk * 8 + tg + 4) * LV + j * 8 + g];
      }
#pragma unroll
      for (int j = 0; j < 16; j++) mma_tf32(o[j], af, bf[j]);
    }
  }

  // ---- epilogue: normalize + residual ----
  {
    float invA = 1.f / lA, invB = 1.f / lB;
    const int rA = q0 + row0 + g, rB = rA + 8;
#pragma unroll
    for (int j = 0; j < 16; j++) {
      int c = j * 8 + 2 * tg;
      size_t baseA = ((size_t)b * S_ + rA) * D_ + (size_t)h * E_ + c;
      size_t baseB = ((size_t)b * S_ + rB) * D_ + (size_t)h * E_ + c;
      float2 mAv = *(const float2*)(modin + baseA);
      float2 mBv = *(const float2*)(modin + baseB);
      float2 oA = make_float2(mAv.x + o[j][0] * invA, mAv.y + o[j][1] * invA);
      float2 oB = make_float2(mBv.x + o[j][2] * invB, mBv.y + o[j][3] * invB);
      *(float2*)(modout + baseA) = oA;
      *(float2*)(modout + baseB) = oB;
    }
  }
}

// ============================================================
extern "C" void kernel_launch(void* const* d_in, const int* in_sizes, int n_in,
                              void* d_out, int out_size) {
  const float* x     = (const float*)d_in[0];
  const float* W_in  = (const float*)d_in[1];
  const float* gamma = (const float*)d_in[2];
  const float* beta  = (const float*)d_in[3];
  const float* Wq    = (const float*)d_in[4];
  const float* Wk    = (const float*)d_in[5];
  const float* Wv    = (const float*)d_in[6];
  const float* Wf    = (const float*)d_in[7];
  const float* bf    = (const float*)d_in[8];
  float* out = (float*)d_out;

  float *mod, *h, *q, *k, *v, *mod2, *h2;
  cudaGetSymbolAddress((void**)&mod,  g_mod);
  cudaGetSymbolAddress((void**)&h,    g_h);
  cudaGetSymbolAddress((void**)&q,    g_q);
  cudaGetSymbolAddress((void**)&k,    g_k);
  cudaGetSymbolAddress((void**)&v,    g_v);
  cudaGetSymbolAddress((void**)&mod2, g_mod2);
  cudaGetSymbolAddress((void**)&h2,   g_h2);

  cudaFuncSetAttribute(k_attn, cudaFuncAttributeMaxDynamicSharedMemorySize, ATTN_SMEM);

  dim3 gdense(D_ / GBN, NT_ / GBM);     // (8, 64)
  k_gemm_dense<<<gdense, 256>>>(x, W_in, mod);

  k_ln<<<NT_, 256>>>(mod, h, gamma, beta);

  dim3 gqkv(S_ / GBM, B_ * H_, 3);      // (16, 32, 3)
  k_gemm_qkv<<<gqkv, 256>>>(h, Wq, Wk, Wv, q, k, v);

  dim3 gattn(S_ / QT, H_, B_);          // (16, 8, 4)
  k_attn<<<gattn, 256, ATTN_SMEM>>>(q, k, v, mod, mod2);

  k_ln<<<NT_, 256>>>(mod2, h2, gamma, beta);

  k_gemm_ffn<<<gdense, 256>>>(h2, Wf, bf, mod2, out);
}

// round 12
// speedup vs baseline: 1.2284x; 1.0138x over previous
#include <cuda_runtime.h>
#include <math.h>
#include <stdint.h>

// ---------------- problem constants ----------------
#define D_   1024
#define H_   8
#define E_   128
#define B_   4
#define S_   2048
#define NT_  (B_ * S_)
#define EPS_ 1e-6f

// ---------------- device scratch ----------------
__device__ float g_mod [NT_ * D_];
__device__ float g_h   [NT_ * D_];
__device__ float g_q   [NT_ * D_];
__device__ float g_k   [NT_ * D_];
__device__ float g_v   [NT_ * D_];
__device__ float g_mod2[NT_ * D_];
__device__ float g_h2  [NT_ * D_];
__device__ float g_xt  [NT_ * D_];     // tf32-converted x
__device__ float g_wint[D_ * D_];      // tf32 W_in
__device__ float g_wft [D_ * D_];      // tf32 Wf
__device__ float g_wqt [H_ * E_ * E_];
__device__ float g_wkt [H_ * E_ * E_];
__device__ float g_wvt [H_ * E_ * E_];

__device__ __forceinline__ float elu1(float x) { return x > 0.f ? x : expm1f(x); }

__device__ __forceinline__ float f2tf(float f) {
  uint32_t u;
  asm("cvt.rna.tf32.f32 %0, %1;" : "=r"(u) : "f"(f));
  return __uint_as_float(u);
}
__device__ __forceinline__ uint32_t tf32bits(float f) {
  uint32_t u;
  asm("cvt.rna.tf32.f32 %0, %1;" : "=r"(u) : "f"(f));
  return u;
}
__device__ __forceinline__ float4 tf32x4(float4 v) {
  return make_float4(f2tf(v.x), f2tf(v.y), f2tf(v.z), f2tf(v.w));
}

__device__ __forceinline__ void mma_tf32(float* d, const uint32_t* a, const uint32_t* b) {
  asm volatile(
      "mma.sync.aligned.m16n8k8.row.col.f32.tf32.tf32.f32 "
      "{%0,%1,%2,%3}, {%4,%5,%6,%7}, {%8,%9}, {%0,%1,%2,%3};"
      : "+f"(d[0]), "+f"(d[1]), "+f"(d[2]), "+f"(d[3])
      : "r"(a[0]), "r"(a[1]), "r"(a[2]), "r"(a[3]), "r"(b[0]), "r"(b[1]));
}

__device__ __forceinline__ void cp16(float* s, const float* g) {
  uint32_t sa = (uint32_t)__cvta_generic_to_shared(s);
  asm volatile("cp.async.cg.shared.global [%0], [%1], 16;" :: "r"(sa), "l"(g));
}
#define CP_COMMIT() asm volatile("cp.async.commit_group;")
#define CP_WAIT0()  asm volatile("cp.async.wait_group 0;")

// ============================================================
// prep: elementwise RNA tf32 conversion (float4 per thread)
// ============================================================
__global__ void k_cvt(const float* __restrict__ in, float* __restrict__ out, int n4) {
  int i = blockIdx.x * blockDim.x + threadIdx.x;
  if (i < n4) ((float4*)out)[i] = tf32x4(((const float4*)in)[i]);
}

// ============================================================
// TF32 GEMM, cp.async double-buffered, operands pre-converted
// (raw loads, zero cvt in loop). 128x128x32, 8 warps (2x4).
// ============================================================
#define GBM 128
#define GBN 128
#define GBK 32
#define LDA_S 36
#define LDB_S 136
#define GEMM_SMEM ((2 * GBM * LDA_S + 2 * GBK * LDB_S) * 4)

template <bool FFN, bool OUT_TF32>
__device__ __forceinline__ void gemm_core(
    const float* __restrict__ A, int lda,
    const float* __restrict__ Bm, int ldb,
    float* __restrict__ C, int ldc, int K,
    const float* __restrict__ bias, const float* __restrict__ resid) {
  extern __shared__ float smg[];
  float* As = smg;                       // [2][GBM*LDA_S]
  float* Bs = smg + 2 * GBM * LDA_S;     // [2][GBK*LDB_S]

  const int t = threadIdx.x;
  const int lane = t & 31, wid = t >> 5;
  const int g = lane >> 2, tg = lane & 3;
  const int wr = wid >> 2, wc = wid & 3;

  const int a_r = t >> 3;        // 0..31
  const int a_c = (t & 7) * 4;   // 0..28
  const int b_r = t >> 5;        // 0..7
  const int b_c = (t & 31) * 4;  // 0..124

  float acc[4][4][4];
#pragma unroll
  for (int i = 0; i < 4; i++)
#pragma unroll
    for (int j = 0; j < 4; j++)
#pragma unroll
      for (int r = 0; r < 4; r++) acc[i][j][r] = 0.f;

  auto load_stage = [&](int st, int k0) {
    float* as = As + st * GBM * LDA_S;
    float* bs = Bs + st * GBK * LDB_S;
#pragma unroll
    for (int i = 0; i < 4; i++) {
      int r = a_r + i * 32;
      cp16(&as[r * LDA_S + a_c], A + (size_t)r * lda + k0 + a_c);
    }
#pragma unroll
    for (int i = 0; i < 4; i++) {
      int r = b_r + i * 8;
      cp16(&bs[r * LDB_S + b_c], Bm + (size_t)(k0 + r) * ldb + b_c);
    }
  };

  load_stage(0, 0);
  CP_COMMIT();

  for (int k0 = 0; k0 < K; k0 += GBK) {
    const int cur = (k0 / GBK) & 1;
    CP_WAIT0();
    __syncthreads();           // stage cur ready; prev iter's reads done
    if (k0 + GBK < K) {
      load_stage(cur ^ 1, k0 + GBK);
      CP_COMMIT();
    }
    const uint32_t* as = (const uint32_t*)(As + cur * GBM * LDA_S);
    const uint32_t* bs = (const uint32_t*)(Bs + cur * GBK * LDB_S);
#pragma unroll
    for (int kk = 0; kk < GBK; kk += 8) {
      uint32_t af[4][4], bf[4][2];
#pragma unroll
      for (int i = 0; i < 4; i++) {
        int r0 = wr * 64 + i * 16;
        af[i][0] = as[(r0 + g) * LDA_S + kk + tg];
        af[i][1] = as[(r0 + g + 8) * LDA_S + kk + tg];
        af[i][2] = as[(r0 + g) * LDA_S + kk + tg + 4];
        af[i][3] = as[(r0 + g + 8) * LDA_S + kk + tg + 4];
      }
#pragma unroll
      for (int j = 0; j < 4; j++) {
        int c0 = wc * 32 + j * 8;
        bf[j][0] = bs[(kk + tg) * LDB_S + c0 + g];
        bf[j][1] = bs[(kk + tg + 4) * LDB_S + c0 + g];
      }
#pragma unroll
      for (int i = 0; i < 4; i++)
#pragma unroll
        for (int j = 0; j < 4; j++) mma_tf32(acc[i][j], af[i], bf[j]);
    }
  }

  // epilogue
#pragma unroll
  for (int i = 0; i < 4; i++) {
    int rA = wr * 64 + i * 16 + g;
    int rB = rA + 8;
#pragma unroll
    for (int j = 0; j < 4; j++) {
      int c = wc * 32 + j * 8 + 2 * tg;
      float2 o0 = make_float2(acc[i][j][0], acc[i][j][1]);
      float2 o1 = make_float2(acc[i][j][2], acc[i][j][3]);
      if (FFN) {
        float2 bv = *(const float2*)(bias + c);
        float2 r0 = *(const float2*)(resid + (size_t)rA * ldc + c);
        float2 r1 = *(const float2*)(resid + (size_t)rB * ldc + c);
        o0.x = r0.x + elu1(o0.x + bv.x);
        o0.y = r0.y + elu1(o0.y + bv.y);
        o1.x = r1.x + elu1(o1.x + bv.x);
        o1.y = r1.y + elu1(o1.y + bv.y);
      }
      if (OUT_TF32) {
        o0.x = f2tf(o0.x); o0.y = f2tf(o0.y);
        o1.x = f2tf(o1.x); o1.y = f2tf(o1.y);
      }
      *(float2*)(C + (size_t)rA * ldc + c) = o0;
      *(float2*)(C + (size_t)rB * ldc + c) = o1;
    }
  }
}

__global__ void __launch_bounds__(256) k_gemm_dense(const float* __restrict__ A,
                                                    const float* __restrict__ W,
                                                    float* __restrict__ C) {
  const size_t moff = (size_t)blockIdx.y * GBM * D_;
  gemm_core<false, false>(A + moff, D_, W + blockIdx.x * GBN, D_,
                          C + moff + blockIdx.x * GBN, D_, D_, nullptr, nullptr);
}

__global__ void __launch_bounds__(256) k_gemm_ffn(const float* __restrict__ A,
                                                  const float* __restrict__ W,
                                                  const float* __restrict__ bias,
                                                  const float* __restrict__ resid,
                                                  float* __restrict__ C) {
  const size_t moff = (size_t)blockIdx.y * GBM * D_;
  const size_t off = moff + blockIdx.x * GBN;
  gemm_core<true, false>(A + moff, D_, W + blockIdx.x * GBN, D_, C + off, D_, D_,
                         bias + blockIdx.x * GBN, resid + off);
}

// fused Q/K/V head projections, epilogue writes RNA tf32
__global__ void __launch_bounds__(256) k_gemm_qkv(const float* __restrict__ Hm,
                                                  const float* __restrict__ Wq,
                                                  const float* __restrict__ Wk,
                                                  const float* __restrict__ Wv,
                                                  float* __restrict__ Oq,
                                                  float* __restrict__ Ok,
                                                  float* __restrict__ Ov) {
  const int which = blockIdx.z;
  const float* W = which == 0 ? Wq : (which == 1 ? Wk : Wv);
  float* Out = which == 0 ? Oq : (which == 1 ? Ok : Ov);
  const int bh = blockIdx.y;
  const int b = bh >> 3, h = bh & 7;
  const float* A = Hm + ((size_t)b * S_ + (size_t)blockIdx.x * GBM) * D_ + h * E_;
  const float* Wp = W + h * E_ * E_;
  float* C = Out + ((size_t)bh * S_ + (size_t)blockIdx.x * GBM) * E_;
  gemm_core<false, true>(A, D_, Wp, E_, C, E_, E_, nullptr, nullptr);
}

// ============================================================
// LayerNorm over last dim (1024); output written as RNA tf32
// (it is only ever consumed as a GEMM A-operand).
// ============================================================
__global__ void __launch_bounds__(256) k_ln(const float* __restrict__ in,
                                            float* __restrict__ out,
                                            const float* __restrict__ gamma,
                                            const float* __restrict__ beta) {
  const size_t row = blockIdx.x;
  const int t = threadIdx.x;
  float4 v = ((const float4*)(in + row * D_))[t];
  float s  = v.x + v.y + v.z + v.w;
  float s2 = v.x * v.x + v.y * v.y + v.z * v.z + v.w * v.w;
#pragma unroll
  for (int off = 16; off; off >>= 1) {
    s  += __shfl_xor_sync(0xffffffffu, s, off);
    s2 += __shfl_xor_sync(0xffffffffu, s2, off);
  }
  __shared__ float sb[16];
  if ((t & 31) == 0) { sb[t >> 5] = s; sb[(t >> 5) + 8] = s2; }
  __syncthreads();
  float tot = 0.f, tot2 = 0.f;
#pragma unroll
  for (int i = 0; i < 8; i++) { tot += sb[i]; tot2 += sb[i + 8]; }
  const float mean = tot * (1.f / D_);
  const float var  = tot2 * (1.f / D_) - mean * mean;
  const float inv  = rsqrtf(var + EPS_);
  float4 gm = ((const float4*)gamma)[t];
  float4 bb = ((const float4*)beta)[t];
  float4 o;
  o.x = (v.x - mean) * inv * gm.x + bb.x;
  o.y = (v.y - mean) * inv * gm.y + bb.y;
  o.z = (v.z - mean) * inv * gm.z + bb.z;
  o.w = (v.w - mean) * inv * gm.w + bb.w;
  ((float4*)(out + row * D_))[t] = tf32x4(o);
}

// ============================================================
// Flash attention (R10 structure). Q/K/V arrive pre-converted
// RNA tf32 from the QKV epilogue -> zero cvt except P.
// QT=128, KT=64, 8 warps, warp owns 16 rows, cp.async K/V,
// register softmax, one block barrier per KV tile.
// ============================================================
#define QT 128
#define KTT 64
#define NKT (S_ / KTT)
#define LK 132
#define LV 136
#define LP 68
#define ATTN_SMEM ((2 * 64 * LK + 2 * 64 * LV + QT * LP) * 4)

__global__ void __launch_bounds__(256) k_attn(const float* __restrict__ Qg,
                                              const float* __restrict__ Kg,
                                              const float* __restrict__ Vg,
                                              const float* __restrict__ modin,
                                              float* __restrict__ modout) {
  extern __shared__ float sm[];
  float* k_s = sm;                              // [2][64][LK]
  float* v_s = sm + 2 * 64 * LK;                // [2][64][LV]
  float* p_s = sm + 2 * 64 * LK + 2 * 64 * LV;  // [128][LP]

  const int t = threadIdx.x;
  const int lane = t & 31, w = t >> 5;
  const int g = lane >> 2, tg = lane & 3;
  const int row0 = w * 16;

  const int q0 = blockIdx.x * QT;
  const int h = blockIdx.y, b = blockIdx.z;
  const size_t bh = (size_t)b * H_ + h;

  const float* Kp = Kg + bh * S_ * E_;
  const float* Vp = Vg + bh * S_ * E_;

  const int ldrow = t >> 5, ldcol = (t & 31) * 4;

  // ---- stage Q (already tf32) via smem scratch, then into registers ----
  {
    const float* Qp = Qg + (bh * S_ + q0) * E_;
#pragma unroll
    for (int i = 0; i < 16; i++) {
      int r = ldrow + i * 8;
      *(float4*)&sm[r * 132 + ldcol] = *(const float4*)(Qp + (size_t)r * E_ + ldcol);
    }
  }
  __syncthreads();

  uint32_t qf[16][4];
  {
    const uint32_t* qs = (const uint32_t*)sm;
#pragma unroll
    for (int kk = 0; kk < 16; kk++) {
      qf[kk][0] = qs[(row0 + g) * 132 + kk * 8 + tg];
      qf[kk][1] = qs[(row0 + g + 8) * 132 + kk * 8 + tg];
      qf[kk][2] = qs[(row0 + g) * 132 + kk * 8 + tg + 4];
      qf[kk][3] = qs[(row0 + g + 8) * 132 + kk * 8 + tg + 4];
    }
  }
  __syncthreads();

  auto load_kv = [&](int st, int kt) {
    float* ks = k_s + st * 64 * LK;
    float* vs = v_s + st * 64 * LV;
    const float* kb = Kp + (size_t)kt * KTT * E_;
    const float* vb = Vp + (size_t)kt * KTT * E_;
#pragma unroll
    for (int i = 0; i < 8; i++) {
      int r = ldrow + i * 8;
      cp16(&ks[r * LK + ldcol], kb + (size_t)r * E_ + ldcol);
      cp16(&vs[r * LV + ldcol], vb + (size_t)r * E_ + ldcol);
    }
  };

  load_kv(0, 0);
  CP_COMMIT();

  float o[16][4];
#pragma unroll
  for (int j = 0; j < 16; j++)
#pragma unroll
    for (int r = 0; r < 4; r++) o[j][r] = 0.f;

  float mA = -1e30f, mB = -1e30f, lA = 0.f, lB = 0.f;

  for (int kt = 0; kt < NKT; kt++) {
    const int cur = kt & 1;
    CP_WAIT0();
    __syncthreads();
    if (kt + 1 < NKT) {
      load_kv(cur ^ 1, kt + 1);
      CP_COMMIT();
    }
    const uint32_t* ks = (const uint32_t*)(k_s + cur * 64 * LK);
    const uint32_t* vs = (const uint32_t*)(v_s + cur * 64 * LV);

    // ---- phase A: scores (16 x 64) = Q K^T ----
    float sc[8][4];
#pragma unroll
    for (int j = 0; j < 8; j++)
#pragma unroll
      for (int r = 0; r < 4; r++) sc[j][r] = 0.f;

#pragma unroll
    for (int kk = 0; kk < 16; kk++) {
      uint32_t bf[8][2];
#pragma unroll
      for (int j = 0; j < 8; j++) {
        bf[j][0] = ks[(j * 8 + g) * LK + kk * 8 + tg];
        bf[j][1] = ks[(j * 8 + g) * LK + kk * 8 + tg + 4];
      }
#pragma unroll
      for (int j = 0; j < 8; j++) mma_tf32(sc[j], qf[kk], bf[j]);
    }

    // ---- register softmax ----
    {
      float mtA = -1e30f, mtB = -1e30f;
#pragma unroll
      for (int j = 0; j < 8; j++) {
        mtA = fmaxf(mtA, fmaxf(sc[j][0], sc[j][1]));
        mtB = fmaxf(mtB, fmaxf(sc[j][2], sc[j][3]));
      }
      mtA = fmaxf(mtA, __shfl_xor_sync(0xffffffffu, mtA, 1));
      mtA = fmaxf(mtA, __shfl_xor_sync(0xffffffffu, mtA, 2));
      mtB = fmaxf(mtB, __shfl_xor_sync(0xffffffffu, mtB, 1));
      mtB = fmaxf(mtB, __shfl_xor_sync(0xffffffffu, mtB, 2));
      float mnA = fmaxf(mA, mtA), mnB = fmaxf(mB, mtB);
      float aA = __expf(mA - mnA), aB = __expf(mB - mnB);
      mA = mnA; mB = mnB;
      float sA = 0.f, sB = 0.f;
#pragma unroll
      for (int j = 0; j < 8; j++) {
        sc[j][0] = __expf(sc[j][0] - mnA);
        sc[j][1] = __expf(sc[j][1] - mnA);
        sc[j][2] = __expf(sc[j][2] - mnB);
        sc[j][3] = __expf(sc[j][3] - mnB);
        sA += sc[j][0] + sc[j][1];
        sB += sc[j][2] + sc[j][3];
      }
      sA += __shfl_xor_sync(0xffffffffu, sA, 1);
      sA += __shfl_xor_sync(0xffffffffu, sA, 2);
      sB += __shfl_xor_sync(0xffffffffu, sB, 1);
      sB += __shfl_xor_sync(0xffffffffu, sB, 2);
      lA = lA * aA + sA;
      lB = lB * aB + sB;
#pragma unroll
      for (int j = 0; j < 16; j++) {
        o[j][0] *= aA; o[j][1] *= aA;
        o[j][2] *= aB; o[j][3] *= aB;
      }
    }

    // ---- write P (RNA tf32) to warp-private smem rows ----
#pragma unroll
    for (int j = 0; j < 8; j++) {
      int c = j * 8 + 2 * tg;
      uint32_t* pA = (uint32_t*)&p_s[(row0 + g) * LP + c];
      uint32_t* pB = (uint32_t*)&p_s[(row0 + g + 8) * LP + c];
      pA[0] = tf32bits(sc[j][0]); pA[1] = tf32bits(sc[j][1]);
      pB[0] = tf32bits(sc[j][2]); pB[1] = tf32bits(sc[j][3]);
    }
    __syncwarp();

    // ---- phase B: O (16 x 128) += P V ----
    const uint32_t* ps = (const uint32_t*)p_s;
#pragma unroll
    for (int kk = 0; kk < 8; kk++) {
      uint32_t af[4];
      af[0] = ps[(row0 + g) * LP + kk * 8 + tg];
      af[1] = ps[(row0 + g + 8) * LP + kk * 8 + tg];
      af[2] = ps[(row0 + g) * LP + kk * 8 + tg + 4];
      af[3] = ps[(row0 + g + 8) * LP + kk * 8 + tg + 4];
      uint32_t bf[16][2];
#pragma unroll
      for (int j = 0; j < 16; j++) {
        bf[j][0] = vs[(kk * 8 + tg) * LV + j * 8 + g];
        bf[j][1] = vs[(kk * 8 + tg + 4) * LV + j * 8 + g];
      }
#pragma unroll
      for (int j = 0; j < 16; j++) mma_tf32(o[j], af, bf[j]);
    }
  }

  // ---- epilogue: normalize + residual ----
  {
    float invA = 1.f / lA, invB = 1.f / lB;
    const int rA = q0 + row0 + g, rB = rA + 8;
#pragma unroll
    for (int j = 0; j < 16; j++) {
      int c = j * 8 + 2 * tg;
      size_t baseA = ((size_t)b * S_ + rA) * D_ + (size_t)h * E_ + c;
      size_t baseB = ((size_t)b * S_ + rB) * D_ + (size_t)h * E_ + c;
      float2 mAv = *(const float2*)(modin + baseA);
      float2 mBv = *(const float2*)(modin + baseB);
      float2 oA = make_float2(mAv.x + o[j][0] * invA, mAv.y + o[j][1] * invA);
      float2 oB = make_float2(mBv.x + o[j][2] * invB, mBv.y + o[j][3] * invB);
      *(float2*)(modout + baseA) = oA;
      *(float2*)(modout + baseB) = oB;
    }
  }
}

// ============================================================
extern "C" void kernel_launch(void* const* d_in, const int* in_sizes, int n_in,
                              void* d_out, int out_size) {
  const float* x     = (const float*)d_in[0];
  const float* W_in  = (const float*)d_in[1];
  const float* gamma = (const float*)d_in[2];
  const float* beta  = (const float*)d_in[3];
  const float* Wq    = (const float*)d_in[4];
  const float* Wk    = (const float*)d_in[5];
  const float* Wv    = (const float*)d_in[6];
  const float* Wf    = (const float*)d_in[7];
  const float* bf    = (const float*)d_in[8];
  float* out = (float*)d_out;

  float *mod, *h, *q, *k, *v, *mod2, *h2;
  float *xt, *wint, *wft, *wqt, *wkt, *wvt;
  cudaGetSymbolAddress((void**)&mod,  g_mod);
  cudaGetSymbolAddress((void**)&h,    g_h);
  cudaGetSymbolAddress((void**)&q,    g_q);
  cudaGetSymbolAddress((void**)&k,    g_k);
  cudaGetSymbolAddress((void**)&v,    g_v);
  cudaGetSymbolAddress((void**)&mod2, g_mod2);
  cudaGetSymbolAddress((void**)&h2,   g_h2);
  cudaGetSymbolAddress((void**)&xt,   g_xt);
  cudaGetSymbolAddress((void**)&wint, g_wint);
  cudaGetSymbolAddress((void**)&wft,  g_wft);
  cudaGetSymbolAddress((void**)&wqt,  g_wqt);
  cudaGetSymbolAddress((void**)&wkt,  g_wkt);
  cudaGetSymbolAddress((void**)&wvt,  g_wvt);

  cudaFuncSetAttribute(k_gemm_dense, cudaFuncAttributeMaxDynamicSharedMemorySize, GEMM_SMEM);
  cudaFuncSetAttribute(k_gemm_ffn,   cudaFuncAttributeMaxDynamicSharedMemorySize, GEMM_SMEM);
  cudaFuncSetAttribute(k_gemm_qkv,   cudaFuncAttributeMaxDynamicSharedMemorySize, GEMM_SMEM);
  cudaFuncSetAttribute(k_attn,       cudaFuncAttributeMaxDynamicSharedMemorySize, ATTN_SMEM);

  // ---- prep: RNA tf32 conversions ----
  k_cvt<<<(NT_ * D_ / 4 + 255) / 256, 256>>>(x, xt, NT_ * D_ / 4);
  k_cvt<<<(D_ * D_ / 4 + 255) / 256, 256>>>(W_in, wint, D_ * D_ / 4);
  k_cvt<<<(D_ * D_ / 4 + 255) / 256, 256>>>(Wf, wft, D_ * D_ / 4);
  k_cvt<<<(H_ * E_ * E_ / 4 + 255) / 256, 256>>>(Wq, wqt, H_ * E_ * E_ / 4);
  k_cvt<<<(H_ * E_ * E_ / 4 + 255) / 256, 256>>>(Wk, wkt, H_ * E_ * E_ / 4);
  k_cvt<<<(H_ * E_ * E_ / 4 + 255) / 256, 256>>>(Wv, wvt, H_ * E_ * E_ / 4);

  dim3 gdense(D_ / GBN, NT_ / GBM);     // (8, 64)
  k_gemm_dense<<<gdense, 256, GEMM_SMEM>>>(xt, wint, mod);

  k_ln<<<NT_, 256>>>(mod, h, gamma, beta);

  dim3 gqkv(S_ / GBM, B_ * H_, 3);      // (16, 32, 3)
  k_gemm_qkv<<<gqkv, 256, GEMM_SMEM>>>(h, wqt, wkt, wvt, q, k, v);

  dim3 gattn(S_ / QT, H_, B_);          // (16, 8, 4)
  k_attn<<<gattn, 256, ATTN_SMEM>>>(q, k, v, mod, mod2);

  k_ln<<<NT_, 256>>>(mod2, h2, gamma, beta);

  k_gemm_ffn<<<gdense, 256, GEMM_SMEM>>>(h2, wft, bf, mod2, out);
}

// round 13
// speedup vs baseline: 1.2427x; 1.0116x over previous
#include <cuda_runtime.h>
#include <math.h>
#include <stdint.h>

// ---------------- problem constants ----------------
#define D_   1024
#define H_   8
#define E_   128
#define B_   4
#define S_   2048
#define NT_  (B_ * S_)
#define EPS_ 1e-6f

// ---------------- device scratch ----------------
__device__ float g_mod [NT_ * D_];
__device__ float g_h   [NT_ * D_];
__device__ float g_q   [NT_ * D_];
__device__ float g_k   [NT_ * D_];
__device__ float g_v   [NT_ * D_];
__device__ float g_mod2[NT_ * D_];
__device__ float g_h2  [NT_ * D_];
__device__ float g_xt  [NT_ * D_];
__device__ float g_wint[D_ * D_];
__device__ float g_wft [D_ * D_];
__device__ float g_wqt [H_ * E_ * E_];
__device__ float g_wkt [H_ * E_ * E_];
__device__ float g_wvt [H_ * E_ * E_];

__device__ __forceinline__ float elu1(float x) { return x > 0.f ? x : expm1f(x); }

__device__ __forceinline__ float f2tf(float f) {
  uint32_t u;
  asm("cvt.rna.tf32.f32 %0, %1;" : "=r"(u) : "f"(f));
  return __uint_as_float(u);
}
__device__ __forceinline__ uint32_t tf32bits(float f) {
  uint32_t u;
  asm("cvt.rna.tf32.f32 %0, %1;" : "=r"(u) : "f"(f));
  return u;
}
__device__ __forceinline__ float4 tf32x4(float4 v) {
  return make_float4(f2tf(v.x), f2tf(v.y), f2tf(v.z), f2tf(v.w));
}

__device__ __forceinline__ void mma_tf32(float* d, const uint32_t* a, const uint32_t* b) {
  asm volatile(
      "mma.sync.aligned.m16n8k8.row.col.f32.tf32.tf32.f32 "
      "{%0,%1,%2,%3}, {%4,%5,%6,%7}, {%8,%9}, {%0,%1,%2,%3};"
      : "+f"(d[0]), "+f"(d[1]), "+f"(d[2]), "+f"(d[3])
      : "r"(a[0]), "r"(a[1]), "r"(a[2]), "r"(a[3]), "r"(b[0]), "r"(b[1]));
}

__device__ __forceinline__ void cp16(float* s, const float* g) {
  uint32_t sa = (uint32_t)__cvta_generic_to_shared(s);
  asm volatile("cp.async.cg.shared.global [%0], [%1], 16;" :: "r"(sa), "l"(g));
}
#define CP_COMMIT() asm volatile("cp.async.commit_group;")
#define CP_WAIT0()  asm volatile("cp.async.wait_group 0;")
#define CP_WAIT1()  asm volatile("cp.async.wait_group 1;")

// ============================================================
// prep: elementwise RNA tf32 conversion
// ============================================================
__global__ void k_cvt(const float* __restrict__ in, float* __restrict__ out, int n4) {
  int i = blockIdx.x * blockDim.x + threadIdx.x;
  if (i < n4) ((float4*)out)[i] = tf32x4(((const float4*)in)[i]);
}

// fused cvt for the three head-weight tensors (equal sizes)
__global__ void k_cvt3(const float* __restrict__ a, const float* __restrict__ b,
                       const float* __restrict__ c, float* __restrict__ oa,
                       float* __restrict__ ob, float* __restrict__ oc, int n4) {
  int i = blockIdx.x * blockDim.x + threadIdx.x;
  if (i >= n4) return;
  const float* in = blockIdx.y == 0 ? a : (blockIdx.y == 1 ? b : c);
  float* out = blockIdx.y == 0 ? oa : (blockIdx.y == 1 ? ob : oc);
  ((float4*)out)[i] = tf32x4(((const float4*)in)[i]);
}

// ============================================================
// TF32 GEMM, 3-stage cp.async pipeline, operands pre-converted.
// 128x128x32, 8 warps (2x4), warp tile 64x32.
// ============================================================
#define GBM 128
#define GBN 128
#define GBK 32
#define LDA_S 36
#define LDB_S 136
#define ST_SZ (GBM * LDA_S + GBK * LDB_S)
#define GEMM_SMEM (3 * ST_SZ * 4)

template <bool FFN, bool OUT_TF32>
__device__ __forceinline__ void gemm_core(
    const float* __restrict__ A, int lda,
    const float* __restrict__ Bm, int ldb,
    float* __restrict__ C, int ldc, int K,
    const float* __restrict__ bias, const float* __restrict__ resid) {
  extern __shared__ float smg[];

  const int t = threadIdx.x;
  const int lane = t & 31, wid = t >> 5;
  const int g = lane >> 2, tg = lane & 3;
  const int wr = wid >> 2, wc = wid & 3;

  const int a_r = t >> 3;        // 0..31
  const int a_c = (t & 7) * 4;   // 0..28
  const int b_r = t >> 5;        // 0..7
  const int b_c = (t & 31) * 4;  // 0..124

  float acc[4][4][4];
#pragma unroll
  for (int i = 0; i < 4; i++)
#pragma unroll
    for (int j = 0; j < 4; j++)
#pragma unroll
      for (int r = 0; r < 4; r++) acc[i][j][r] = 0.f;

  auto load_stage = [&](int st, int k0) {
    float* as = smg + st * ST_SZ;
    float* bs = as + GBM * LDA_S;
#pragma unroll
    for (int i = 0; i < 4; i++) {
      int r = a_r + i * 32;
      cp16(&as[r * LDA_S + a_c], A + (size_t)r * lda + k0 + a_c);
    }
#pragma unroll
    for (int i = 0; i < 4; i++) {
      int r = b_r + i * 8;
      cp16(&bs[r * LDB_S + b_c], Bm + (size_t)(k0 + r) * ldb + b_c);
    }
  };

  load_stage(0, 0);
  CP_COMMIT();
  if (GBK < K) {
    load_stage(1, GBK);
    CP_COMMIT();
  }

  int cur = 0;
  for (int k0 = 0; k0 < K; k0 += GBK) {
    CP_WAIT1();            // stage cur complete (<=1 group pending)
    __syncthreads();       // all threads see stage cur; prev iter reads done
    if (k0 + 2 * GBK < K) {
      int nxt = cur + 2; if (nxt >= 3) nxt -= 3;
      load_stage(nxt, k0 + 2 * GBK);
      CP_COMMIT();
    }
    const uint32_t* as = (const uint32_t*)(smg + cur * ST_SZ);
    const uint32_t* bs = as + GBM * LDA_S;
#pragma unroll
    for (int kk = 0; kk < GBK; kk += 8) {
      uint32_t af[4][4], bf[4][2];
#pragma unroll
      for (int i = 0; i < 4; i++) {
        int r0 = wr * 64 + i * 16;
        af[i][0] = as[(r0 + g) * LDA_S + kk + tg];
        af[i][1] = as[(r0 + g + 8) * LDA_S + kk + tg];
        af[i][2] = as[(r0 + g) * LDA_S + kk + tg + 4];
        af[i][3] = as[(r0 + g + 8) * LDA_S + kk + tg + 4];
      }
#pragma unroll
      for (int j = 0; j < 4; j++) {
        int c0 = wc * 32 + j * 8;
        bf[j][0] = bs[(kk + tg) * LDB_S + c0 + g];
        bf[j][1] = bs[(kk + tg + 4) * LDB_S + c0 + g];
      }
#pragma unroll
      for (int i = 0; i < 4; i++)
#pragma unroll
        for (int j = 0; j < 4; j++) mma_tf32(acc[i][j], af[i], bf[j]);
    }
    if (++cur == 3) cur = 0;
  }

  // epilogue
#pragma unroll
  for (int i = 0; i < 4; i++) {
    int rA = wr * 64 + i * 16 + g;
    int rB = rA + 8;
#pragma unroll
    for (int j = 0; j < 4; j++) {
      int c = wc * 32 + j * 8 + 2 * tg;
      float2 o0 = make_float2(acc[i][j][0], acc[i][j][1]);
      float2 o1 = make_float2(acc[i][j][2], acc[i][j][3]);
      if (FFN) {
        float2 bv = *(const float2*)(bias + c);
        float2 r0 = *(const float2*)(resid + (size_t)rA * ldc + c);
        float2 r1 = *(const float2*)(resid + (size_t)rB * ldc + c);
        o0.x = r0.x + elu1(o0.x + bv.x);
        o0.y = r0.y + elu1(o0.y + bv.y);
        o1.x = r1.x + elu1(o1.x + bv.x);
        o1.y = r1.y + elu1(o1.y + bv.y);
      }
      if (OUT_TF32) {
        o0.x = f2tf(o0.x); o0.y = f2tf(o0.y);
        o1.x = f2tf(o1.x); o1.y = f2tf(o1.y);
      }
      *(float2*)(C + (size_t)rA * ldc + c) = o0;
      *(float2*)(C + (size_t)rB * ldc + c) = o1;
    }
  }
}

__global__ void __launch_bounds__(256) k_gemm_dense(const float* __restrict__ A,
                                                    const float* __restrict__ W,
                                                    float* __restrict__ C) {
  const size_t moff = (size_t)blockIdx.y * GBM * D_;
  gemm_core<false, false>(A + moff, D_, W + blockIdx.x * GBN, D_,
                          C + moff + blockIdx.x * GBN, D_, D_, nullptr, nullptr);
}

__global__ void __launch_bounds__(256) k_gemm_ffn(const float* __restrict__ A,
                                                  const float* __restrict__ W,
                                                  const float* __restrict__ bias,
                                                  const float* __restrict__ resid,
                                                  float* __restrict__ C) {
  const size_t moff = (size_t)blockIdx.y * GBM * D_;
  const size_t off = moff + blockIdx.x * GBN;
  gemm_core<true, false>(A + moff, D_, W + blockIdx.x * GBN, D_, C + off, D_, D_,
                         bias + blockIdx.x * GBN, resid + off);
}

__global__ void __launch_bounds__(256) k_gemm_qkv(const float* __restrict__ Hm,
                                                  const float* __restrict__ Wq,
                                                  const float* __restrict__ Wk,
                                                  const float* __restrict__ Wv,
                                                  float* __restrict__ Oq,
                                                  float* __restrict__ Ok,
                                                  float* __restrict__ Ov) {
  const int which = blockIdx.z;
  const float* W = which == 0 ? Wq : (which == 1 ? Wk : Wv);
  float* Out = which == 0 ? Oq : (which == 1 ? Ok : Ov);
  const int bh = blockIdx.y;
  const int b = bh >> 3, h = bh & 7;
  const float* A = Hm + ((size_t)b * S_ + (size_t)blockIdx.x * GBM) * D_ + h * E_;
  const float* Wp = W + h * E_ * E_;
  float* C = Out + ((size_t)bh * S_ + (size_t)blockIdx.x * GBM) * E_;
  gemm_core<false, true>(A, D_, Wp, E_, C, E_, E_, nullptr, nullptr);
}

// ============================================================
// LayerNorm, warp-per-row (8 rows/block), no block barrier.
// Output written as RNA tf32 (only consumed as GEMM A-operand).
// ============================================================
__global__ void __launch_bounds__(256) k_ln(const float* __restrict__ in,
                                            float* __restrict__ out,
                                            const float* __restrict__ gamma,
                                            const float* __restrict__ beta) {
  const int lane = threadIdx.x & 31;
  const size_t row = (size_t)blockIdx.x * 8 + (threadIdx.x >> 5);
  const float4* ip = (const float4*)(in + row * D_);
  float4 v[8];
  float s = 0.f, s2 = 0.f;
#pragma unroll
  for (int i = 0; i < 8; i++) {
    v[i] = ip[lane + i * 32];
    s  += v[i].x + v[i].y + v[i].z + v[i].w;
    s2 += v[i].x * v[i].x + v[i].y * v[i].y + v[i].z * v[i].z + v[i].w * v[i].w;
  }
#pragma unroll
  for (int off = 16; off; off >>= 1) {
    s  += __shfl_xor_sync(0xffffffffu, s, off);
    s2 += __shfl_xor_sync(0xffffffffu, s2, off);
  }
  const float mean = s * (1.f / D_);
  const float var  = s2 * (1.f / D_) - mean * mean;
  const float inv  = rsqrtf(var + EPS_);
  float4* op = (float4*)(out + row * D_);
#pragma unroll
  for (int i = 0; i < 8; i++) {
    float4 gm = ((const float4*)gamma)[lane + i * 32];
    float4 bb = ((const float4*)beta)[lane + i * 32];
    float4 o;
    o.x = (v[i].x - mean) * inv * gm.x + bb.x;
    o.y = (v[i].y - mean) * inv * gm.y + bb.y;
    o.z = (v[i].z - mean) * inv * gm.z + bb.z;
    o.w = (v[i].w - mean) * inv * gm.w + bb.w;
    op[lane + i * 32] = tf32x4(o);
  }
}

// ============================================================
// Flash attention (R10/R11 structure, unchanged).
// ============================================================
#define QT 128
#define KTT 64
#define NKT (S_ / KTT)
#define LK 132
#define LV 136
#define LP 68
#define ATTN_SMEM ((2 * 64 * LK + 2 * 64 * LV + QT * LP) * 4)

__global__ void __launch_bounds__(256) k_attn(const float* __restrict__ Qg,
                                              const float* __restrict__ Kg,
                                              const float* __restrict__ Vg,
                                              const float* __restrict__ modin,
                                              float* __restrict__ modout) {
  extern __shared__ float sm[];
  float* k_s = sm;                              // [2][64][LK]
  float* v_s = sm + 2 * 64 * LK;                // [2][64][LV]
  float* p_s = sm + 2 * 64 * LK + 2 * 64 * LV;  // [128][LP]

  const int t = threadIdx.x;
  const int lane = t & 31, w = t >> 5;
  const int g = lane >> 2, tg = lane & 3;
  const int row0 = w * 16;

  const int q0 = blockIdx.x * QT;
  const int h = blockIdx.y, b = blockIdx.z;
  const size_t bh = (size_t)b * H_ + h;

  const float* Kp = Kg + bh * S_ * E_;
  const float* Vp = Vg + bh * S_ * E_;

  const int ldrow = t >> 5, ldcol = (t & 31) * 4;

  // stage Q (already tf32) via smem scratch, then into registers
  {
    const float* Qp = Qg + (bh * S_ + q0) * E_;
#pragma unroll
    for (int i = 0; i < 16; i++) {
      int r = ldrow + i * 8;
      *(float4*)&sm[r * 132 + ldcol] = *(const float4*)(Qp + (size_t)r * E_ + ldcol);
    }
  }
  __syncthreads();

  uint32_t qf[16][4];
  {
    const uint32_t* qs = (const uint32_t*)sm;
#pragma unroll
    for (int kk = 0; kk < 16; kk++) {
      qf[kk][0] = qs[(row0 + g) * 132 + kk * 8 + tg];
      qf[kk][1] = qs[(row0 + g + 8) * 132 + kk * 8 + tg];
      qf[kk][2] = qs[(row0 + g) * 132 + kk * 8 + tg + 4];
      qf[kk][3] = qs[(row0 + g + 8) * 132 + kk * 8 + tg + 4];
    }
  }
  __syncthreads();

  auto load_kv = [&](int st, int kt) {
    float* ks = k_s + st * 64 * LK;
    float* vs = v_s + st * 64 * LV;
    const float* kb = Kp + (size_t)kt * KTT * E_;
    const float* vb = Vp + (size_t)kt * KTT * E_;
#pragma unroll
    for (int i = 0; i < 8; i++) {
      int r = ldrow + i * 8;
      cp16(&ks[r * LK + ldcol], kb + (size_t)r * E_ + ldcol);
      cp16(&vs[r * LV + ldcol], vb + (size_t)r * E_ + ldcol);
    }
  };

  load_kv(0, 0);
  CP_COMMIT();

  float o[16][4];
#pragma unroll
  for (int j = 0; j < 16; j++)
#pragma unroll
    for (int r = 0; r < 4; r++) o[j][r] = 0.f;

  float mA = -1e30f, mB = -1e30f, lA = 0.f, lB = 0.f;

  for (int kt = 0; kt < NKT; kt++) {
    const int cur = kt & 1;
    CP_WAIT0();
    __syncthreads();
    if (kt + 1 < NKT) {
      load_kv(cur ^ 1, kt + 1);
      CP_COMMIT();
    }
    const uint32_t* ks = (const uint32_t*)(k_s + cur * 64 * LK);
    const uint32_t* vs = (const uint32_t*)(v_s + cur * 64 * LV);

    // phase A: scores (16 x 64) = Q K^T
    float sc[8][4];
#pragma unroll
    for (int j = 0; j < 8; j++)
#pragma unroll
      for (int r = 0; r < 4; r++) sc[j][r] = 0.f;

#pragma unroll
    for (int kk = 0; kk < 16; kk++) {
      uint32_t bf[8][2];
#pragma unroll
      for (int j = 0; j < 8; j++) {
        bf[j][0] = ks[(j * 8 + g) * LK + kk * 8 + tg];
        bf[j][1] = ks[(j * 8 + g) * LK + kk * 8 + tg + 4];
      }
#pragma unroll
      for (int j = 0; j < 8; j++) mma_tf32(sc[j], qf[kk], bf[j]);
    }

    // register softmax
    {
      float mtA = -1e30f, mtB = -1e30f;
#pragma unroll
      for (int j = 0; j < 8; j++) {
        mtA = fmaxf(mtA, fmaxf(sc[j][0], sc[j][1]));
        mtB = fmaxf(mtB, fmaxf(sc[j][2], sc[j][3]));
      }
      mtA = fmaxf(mtA, __shfl_xor_sync(0xffffffffu, mtA, 1));
      mtA = fmaxf(mtA, __shfl_xor_sync(0xffffffffu, mtA, 2));
      mtB = fmaxf(mtB, __shfl_xor_sync(0xffffffffu, mtB, 1));
      mtB = fmaxf(mtB, __shfl_xor_sync(0xffffffffu, mtB, 2));
      float mnA = fmaxf(mA, mtA), mnB = fmaxf(mB, mtB);
      float aA = __expf(mA - mnA), aB = __expf(mB - mnB);
      mA = mnA; mB = mnB;
      float sA = 0.f, sB = 0.f;
#pragma unroll
      for (int j = 0; j < 8; j++) {
        sc[j][0] = __expf(sc[j][0] - mnA);
        sc[j][1] = __expf(sc[j][1] - mnA);
        sc[j][2] = __expf(sc[j][2] - mnB);
        sc[j][3] = __expf(sc[j][3] - mnB);
        sA += sc[j][0] + sc[j][1];
        sB += sc[j][2] + sc[j][3];
      }
      sA += __shfl_xor_sync(0xffffffffu, sA, 1);
      sA += __shfl_xor_sync(0xffffffffu, sA, 2);
      sB += __shfl_xor_sync(0xffffffffu, sB, 1);
      sB += __shfl_xor_sync(0xffffffffu, sB, 2);
      lA = lA * aA + sA;
      lB = lB * aB + sB;
#pragma unroll
      for (int j = 0; j < 16; j++) {
        o[j][0] *= aA; o[j][1] *= aA;
        o[j][2] *= aB; o[j][3] *= aB;
      }
    }

    // write P (RNA tf32) to warp-private smem rows
#pragma unroll
    for (int j = 0; j < 8; j++) {
      int c = j * 8 + 2 * tg;
      uint32_t* pA = (uint32_t*)&p_s[(row0 + g) * LP + c];
      uint32_t* pB = (uint32_t*)&p_s[(row0 + g + 8) * LP + c];
      pA[0] = tf32bits(sc[j][0]); pA[1] = tf32bits(sc[j][1]);
      pB[0] = tf32bits(sc[j][2]); pB[1] = tf32bits(sc[j][3]);
    }
    __syncwarp();

    // phase B: O (16 x 128) += P V
    const uint32_t* ps = (const uint32_t*)p_s;
#pragma unroll
    for (int kk = 0; kk < 8; kk++) {
      uint32_t af[4];
      af[0] = ps[(row0 + g) * LP + kk * 8 + tg];
      af[1] = ps[(row0 + g + 8) * LP + kk * 8 + tg];
      af[2] = ps[(row0 + g) * LP + kk * 8 + tg + 4];
      af[3] = ps[(row0 + g + 8) * LP + kk * 8 + tg + 4];
      uint32_t bf[16][2];
#pragma unroll
      for (int j = 0; j < 16; j++) {
        bf[j][0] = vs[(kk * 8 + tg) * LV + j * 8 + g];
        bf[j][1] = vs[(kk * 8 + tg + 4) * LV + j * 8 + g];
      }
#pragma unroll
      for (int j = 0; j < 16; j++) mma_tf32(o[j], af, bf[j]);
    }
  }

  // epilogue: normalize + residual
  {
    float invA = 1.f / lA, invB = 1.f / lB;
    const int rA = q0 + row0 + g, rB = rA + 8;
#pragma unroll
    for (int j = 0; j < 16; j++) {
      int c = j * 8 + 2 * tg;
      size_t baseA = ((size_t)b * S_ + rA) * D_ + (size_t)h * E_ + c;
      size_t baseB = ((size_t)b * S_ + rB) * D_ + (size_t)h * E_ + c;
      float2 mAv = *(const float2*)(modin + baseA);
      float2 mBv = *(const float2*)(modin + baseB);
      float2 oA = make_float2(mAv.x + o[j][0] * invA, mAv.y + o[j][1] * invA);
      float2 oB = make_float2(mBv.x + o[j][2] * invB, mBv.y + o[j][3] * invB);
      *(float2*)(modout + baseA) = oA;
      *(float2*)(modout + baseB) = oB;
    }
  }
}

// ============================================================
extern "C" void kernel_launch(void* const* d_in, const int* in_sizes, int n_in,
                              void* d_out, int out_size) {
  const float* x     = (const float*)d_in[0];
  const float* W_in  = (const float*)d_in[1];
  const float* gamma = (const float*)d_in[2];
  const float* beta  = (const float*)d_in[3];
  const float* Wq    = (const float*)d_in[4];
  const float* Wk    = (const float*)d_in[5];
  const float* Wv    = (const float*)d_in[6];
  const float* Wf    = (const float*)d_in[7];
  const float* bf    = (const float*)d_in[8];
  float* out = (float*)d_out;

  float *mod, *h, *q, *k, *v, *mod2, *h2;
  float *xt, *wint, *wft, *wqt, *wkt, *wvt;
  cudaGetSymbolAddress((void**)&mod,  g_mod);
  cudaGetSymbolAddress((void**)&h,    g_h);
  cudaGetSymbolAddress((void**)&q,    g_q);
  cudaGetSymbolAddress((void**)&k,    g_k);
  cudaGetSymbolAddress((void**)&v,    g_v);
  cudaGetSymbolAddress((void**)&mod2, g_mod2);
  cudaGetSymbolAddress((void**)&h2,   g_h2);
  cudaGetSymbolAddress((void**)&xt,   g_xt);
  cudaGetSymbolAddress((void**)&wint, g_wint);
  cudaGetSymbolAddress((void**)&wft,  g_wft);
  cudaGetSymbolAddress((void**)&wqt,  g_wqt);
  cudaGetSymbolAddress((void**)&wkt,  g_wkt);
  cudaGetSymbolAddress((void**)&wvt,  g_wvt);

  cudaFuncSetAttribute(k_gemm_dense, cudaFuncAttributeMaxDynamicSharedMemorySize, GEMM_SMEM);
  cudaFuncSetAttribute(k_gemm_ffn,   cudaFuncAttributeMaxDynamicSharedMemorySize, GEMM_SMEM);
  cudaFuncSetAttribute(k_gemm_qkv,   cudaFuncAttributeMaxDynamicSharedMemorySize, GEMM_SMEM);
  cudaFuncSetAttribute(k_attn,       cudaFuncAttributeMaxDynamicSharedMemorySize, ATTN_SMEM);

  // ---- prep: RNA tf32 conversions ----
  k_cvt<<<(NT_ * D_ / 4 + 255) / 256, 256>>>(x, xt, NT_ * D_ / 4);
  k_cvt<<<(D_ * D_ / 4 + 255) / 256, 256>>>(W_in, wint, D_ * D_ / 4);
  k_cvt<<<(D_ * D_ / 4 + 255) / 256, 256>>>(Wf, wft, D_ * D_ / 4);
  dim3 g3((H_ * E_ * E_ / 4 + 255) / 256, 3);
  k_cvt3<<<g3, 256>>>(Wq, Wk, Wv, wqt, wkt, wvt, H_ * E_ * E_ / 4);

  dim3 gdense(D_ / GBN, NT_ / GBM);     // (8, 64)
  k_gemm_dense<<<gdense, 256, GEMM_SMEM>>>(xt, wint, mod);

  k_ln<<<NT_ / 8, 256>>>(mod, h, gamma, beta);

  dim3 gqkv(S_ / GBM, B_ * H_, 3);      // (16, 32, 3)
  k_gemm_qkv<<<gqkv, 256, GEMM_SMEM>>>(h, wqt, wkt, wvt, q, k, v);

  dim3 gattn(S_ / QT, H_, B_);          // (16, 8, 4)
  k_attn<<<gattn, 256, ATTN_SMEM>>>(q, k, v, mod, mod2);

  k_ln<<<NT_ / 8, 256>>>(mod2, h2, gamma, beta);

  k_gemm_ffn<<<gdense, 256, GEMM_SMEM>>>(h2, wft, bf, mod2, out);
}

// round 14
// speedup vs baseline: 1.6709x; 1.3446x over previous
#include <cuda_runtime.h>
#include <cuda_bf16.h>
#include <math.h>
#include <stdint.h>

// ---------------- problem constants ----------------
#define D_   1024
#define H_   8
#define E_   128
#define B_   4
#define S_   2048
#define NT_  (B_ * S_)
#define EPS_ 1e-6f

// ---------------- device scratch ----------------
__device__ float g_mod [NT_ * D_];
__device__ float g_h   [NT_ * D_];
__device__ float g_q   [NT_ * D_];   // used as bf16 (half the bytes)
__device__ float g_k   [NT_ * D_];
__device__ float g_v   [NT_ * D_];
__device__ float g_mod2[NT_ * D_];
__device__ float g_h2  [NT_ * D_];
__device__ float g_xt  [NT_ * D_];
__device__ float g_wint[D_ * D_];
__device__ float g_wft [D_ * D_];
__device__ float g_wqt [H_ * E_ * E_];
__device__ float g_wkt [H_ * E_ * E_];
__device__ float g_wvt [H_ * E_ * E_];

__device__ __forceinline__ float elu1(float x) { return x > 0.f ? x : expm1f(x); }

__device__ __forceinline__ float f2tf(float f) {
  uint32_t u;
  asm("cvt.rna.tf32.f32 %0, %1;" : "=r"(u) : "f"(f));
  return __uint_as_float(u);
}
__device__ __forceinline__ float4 tf32x4(float4 v) {
  return make_float4(f2tf(v.x), f2tf(v.y), f2tf(v.z), f2tf(v.w));
}
__device__ __forceinline__ uint32_t packbf(float lo, float hi) {
  __nv_bfloat162 p = __floats2bfloat162_rn(lo, hi);  // .x = lo (low half)
  return *(uint32_t*)&p;
}

__device__ __forceinline__ void mma_tf32(float* d, const uint32_t* a, const uint32_t* b) {
  asm volatile(
      "mma.sync.aligned.m16n8k8.row.col.f32.tf32.tf32.f32 "
      "{%0,%1,%2,%3}, {%4,%5,%6,%7}, {%8,%9}, {%0,%1,%2,%3};"
      : "+f"(d[0]), "+f"(d[1]), "+f"(d[2]), "+f"(d[3])
      : "r"(a[0]), "r"(a[1]), "r"(a[2]), "r"(a[3]), "r"(b[0]), "r"(b[1]));
}
__device__ __forceinline__ void mma_bf16(float* d, const uint32_t* a, const uint32_t* b) {
  asm volatile(
      "mma.sync.aligned.m16n8k16.row.col.f32.bf16.bf16.f32 "
      "{%0,%1,%2,%3}, {%4,%5,%6,%7}, {%8,%9}, {%0,%1,%2,%3};"
      : "+f"(d[0]), "+f"(d[1]), "+f"(d[2]), "+f"(d[3])
      : "r"(a[0]), "r"(a[1]), "r"(a[2]), "r"(a[3]), "r"(b[0]), "r"(b[1]));
}

__device__ __forceinline__ void cp16(float* s, const float* g) {
  uint32_t sa = (uint32_t)__cvta_generic_to_shared(s);
  asm volatile("cp.async.cg.shared.global [%0], [%1], 16;" :: "r"(sa), "l"(g));
}
#define CP_COMMIT() asm volatile("cp.async.commit_group;")
#define CP_WAIT0()  asm volatile("cp.async.wait_group 0;")
#define CP_WAIT1()  asm volatile("cp.async.wait_group 1;")

// ============================================================
// prep: elementwise RNA tf32 conversion
// ============================================================
__global__ void k_cvt(const float* __restrict__ in, float* __restrict__ out, int n4) {
  int i = blockIdx.x * blockDim.x + threadIdx.x;
  if (i < n4) ((float4*)out)[i] = tf32x4(((const float4*)in)[i]);
}
__global__ void k_cvt3(const float* __restrict__ a, const float* __restrict__ b,
                       const float* __restrict__ c, float* __restrict__ oa,
                       float* __restrict__ ob, float* __restrict__ oc, int n4) {
  int i = blockIdx.x * blockDim.x + threadIdx.x;
  if (i >= n4) return;
  const float* in = blockIdx.y == 0 ? a : (blockIdx.y == 1 ? b : c);
  float* out = blockIdx.y == 0 ? oa : (blockIdx.y == 1 ? ob : oc);
  ((float4*)out)[i] = tf32x4(((const float4*)in)[i]);
}

// ============================================================
// TF32 GEMM, 3-stage cp.async pipeline, operands pre-converted.
// 128x128x32, 8 warps (2x4), warp tile 64x32.
// MODE: 0 = fp32 out, 1 = fp32 + bias/ELU/residual,
//       2 = bf16 out, 3 = bf16 out, rows pair-interleaved (V).
// ============================================================
#define GBM 128
#define GBN 128
#define GBK 32
#define LDA_S 36
#define LDB_S 136
#define ST_SZ (GBM * LDA_S + GBK * LDB_S)
#define GEMM_SMEM (3 * ST_SZ * 4)

template <int MODE>
__device__ __forceinline__ void gemm_core(
    const float* __restrict__ A, int lda,
    const float* __restrict__ Bm, int ldb,
    void* __restrict__ Cv, int ldc, int K,
    const float* __restrict__ bias, const float* __restrict__ resid) {
  extern __shared__ float smg[];

  const int t = threadIdx.x;
  const int lane = t & 31, wid = t >> 5;
  const int g = lane >> 2, tg = lane & 3;
  const int wr = wid >> 2, wc = wid & 3;

  const int a_r = t >> 3;
  const int a_c = (t & 7) * 4;
  const int b_r = t >> 5;
  const int b_c = (t & 31) * 4;

  float acc[4][4][4];
#pragma unroll
  for (int i = 0; i < 4; i++)
#pragma unroll
    for (int j = 0; j < 4; j++)
#pragma unroll
      for (int r = 0; r < 4; r++) acc[i][j][r] = 0.f;

  auto load_stage = [&](int st, int k0) {
    float* as = smg + st * ST_SZ;
    float* bs = as + GBM * LDA_S;
#pragma unroll
    for (int i = 0; i < 4; i++) {
      int r = a_r + i * 32;
      cp16(&as[r * LDA_S + a_c], A + (size_t)r * lda + k0 + a_c);
    }
#pragma unroll
    for (int i = 0; i < 4; i++) {
      int r = b_r + i * 8;
      cp16(&bs[r * LDB_S + b_c], Bm + (size_t)(k0 + r) * ldb + b_c);
    }
  };

  load_stage(0, 0);
  CP_COMMIT();
  if (GBK < K) {
    load_stage(1, GBK);
    CP_COMMIT();
  }

  int cur = 0;
  for (int k0 = 0; k0 < K; k0 += GBK) {
    CP_WAIT1();
    __syncthreads();
    if (k0 + 2 * GBK < K) {
      int nxt = cur + 2; if (nxt >= 3) nxt -= 3;
      load_stage(nxt, k0 + 2 * GBK);
      CP_COMMIT();
    }
    const uint32_t* as = (const uint32_t*)(smg + cur * ST_SZ);
    const uint32_t* bs = as + GBM * LDA_S;
#pragma unroll
    for (int kk = 0; kk < GBK; kk += 8) {
      uint32_t af[4][4], bf[4][2];
#pragma unroll
      for (int i = 0; i < 4; i++) {
        int r0 = wr * 64 + i * 16;
        af[i][0] = as[(r0 + g) * LDA_S + kk + tg];
        af[i][1] = as[(r0 + g + 8) * LDA_S + kk + tg];
        af[i][2] = as[(r0 + g) * LDA_S + kk + tg + 4];
        af[i][3] = as[(r0 + g + 8) * LDA_S + kk + tg + 4];
      }
#pragma unroll
      for (int j = 0; j < 4; j++) {
        int c0 = wc * 32 + j * 8;
        bf[j][0] = bs[(kk + tg) * LDB_S + c0 + g];
        bf[j][1] = bs[(kk + tg + 4) * LDB_S + c0 + g];
      }
#pragma unroll
      for (int i = 0; i < 4; i++)
#pragma unroll
        for (int j = 0; j < 4; j++) mma_tf32(acc[i][j], af[i], bf[j]);
    }
    if (++cur == 3) cur = 0;
  }

  // epilogue
#pragma unroll
  for (int i = 0; i < 4; i++) {
    int rA = wr * 64 + i * 16 + g;
    int rB = rA + 8;
#pragma unroll
    for (int j = 0; j < 4; j++) {
      int c = wc * 32 + j * 8 + 2 * tg;
      float2 o0 = make_float2(acc[i][j][0], acc[i][j][1]);
      float2 o1 = make_float2(acc[i][j][2], acc[i][j][3]);
      if (MODE == 1) {
        float2 bv = *(const float2*)(bias + c);
        float2 r0 = *(const float2*)(resid + (size_t)rA * ldc + c);
        float2 r1 = *(const float2*)(resid + (size_t)rB * ldc + c);
        o0.x = r0.x + elu1(o0.x + bv.x);
        o0.y = r0.y + elu1(o0.y + bv.y);
        o1.x = r1.x + elu1(o1.x + bv.x);
        o1.y = r1.y + elu1(o1.y + bv.y);
      }
      if (MODE <= 1) {
        float* C = (float*)Cv;
        *(float2*)(C + (size_t)rA * ldc + c) = o0;
        *(float2*)(C + (size_t)rB * ldc + c) = o1;
      } else if (MODE == 2) {
        uint32_t* C = (uint32_t*)Cv;                 // pairs of bf16
        C[(size_t)rA * (ldc / 2) + (c >> 1)] = packbf(o0.x, o0.y);
        C[(size_t)rB * (ldc / 2) + (c >> 1)] = packbf(o1.x, o1.y);
      } else {                                       // MODE 3: V s-pair interleave
        __nv_bfloat16* C = (__nv_bfloat16*)Cv;
        size_t pA = (size_t)(rA >> 1) * 2 * ldc + 2 * c + (rA & 1);
        size_t pB = (size_t)(rB >> 1) * 2 * ldc + 2 * c + (rB & 1);
        C[pA]     = __float2bfloat16_rn(o0.x);
        C[pA + 2] = __float2bfloat16_rn(o0.y);
        C[pB]     = __float2bfloat16_rn(o1.x);
        C[pB + 2] = __float2bfloat16_rn(o1.y);
      }
    }
  }
}

__global__ void __launch_bounds__(256) k_gemm_dense(const float* __restrict__ A,
                                                    const float* __restrict__ W,
                                                    float* __restrict__ C) {
  const size_t moff = (size_t)blockIdx.y * GBM * D_;
  gemm_core<0>(A + moff, D_, W + blockIdx.x * GBN, D_,
               C + moff + blockIdx.x * GBN, D_, D_, nullptr, nullptr);
}

__global__ void __launch_bounds__(256) k_gemm_ffn(const float* __restrict__ A,
                                                  const float* __restrict__ W,
                                                  const float* __restrict__ bias,
                                                  const float* __restrict__ resid,
                                                  float* __restrict__ C) {
  const size_t moff = (size_t)blockIdx.y * GBM * D_;
  const size_t off = moff + blockIdx.x * GBN;
  gemm_core<1>(A + moff, D_, W + blockIdx.x * GBN, D_, C + off, D_, D_,
               bias + blockIdx.x * GBN, resid + off);
}

// fused Q/K/V head projections; outputs bf16 (V pair-interleaved)
__global__ void __launch_bounds__(256) k_gemm_qkv(const float* __restrict__ Hm,
                                                  const float* __restrict__ Wq,
                                                  const float* __restrict__ Wk,
                                                  const float* __restrict__ Wv,
                                                  __nv_bfloat16* __restrict__ Oq,
                                                  __nv_bfloat16* __restrict__ Ok,
                                                  __nv_bfloat16* __restrict__ Ov) {
  const int which = blockIdx.z;
  const int bh = blockIdx.y;
  const int b = bh >> 3, h = bh & 7;
  const float* A = Hm + ((size_t)b * S_ + (size_t)blockIdx.x * GBM) * D_ + h * E_;
  if (which == 0) {
    __nv_bfloat16* C = Oq + ((size_t)bh * S_ + (size_t)blockIdx.x * GBM) * E_;
    gemm_core<2>(A, D_, Wq + h * E_ * E_, E_, C, E_, E_, nullptr, nullptr);
  } else if (which == 1) {
    __nv_bfloat16* C = Ok + ((size_t)bh * S_ + (size_t)blockIdx.x * GBM) * E_;
    gemm_core<2>(A, D_, Wk + h * E_ * E_, E_, C, E_, E_, nullptr, nullptr);
  } else {
    __nv_bfloat16* C = Ov + ((size_t)bh * S_ + (size_t)blockIdx.x * GBM) * E_;
    gemm_core<3>(A, D_, Wv + h * E_ * E_, E_, C, E_, E_, nullptr, nullptr);
  }
}

// ============================================================
// LayerNorm, warp-per-row (8 rows/block); tf32 output.
// ============================================================
__global__ void __launch_bounds__(256) k_ln(const float* __restrict__ in,
                                            float* __restrict__ out,
                                            const float* __restrict__ gamma,
                                            const float* __restrict__ beta) {
  const int lane = threadIdx.x & 31;
  const size_t row = (size_t)blockIdx.x * 8 + (threadIdx.x >> 5);
  const float4* ip = (const float4*)(in + row * D_);
  float4 v[8];
  float s = 0.f, s2 = 0.f;
#pragma unroll
  for (int i = 0; i < 8; i++) {
    v[i] = ip[lane + i * 32];
    s  += v[i].x + v[i].y + v[i].z + v[i].w;
    s2 += v[i].x * v[i].x + v[i].y * v[i].y + v[i].z * v[i].z + v[i].w * v[i].w;
  }
#pragma unroll
  for (int off = 16; off; off >>= 1) {
    s  += __shfl_xor_sync(0xffffffffu, s, off);
    s2 += __shfl_xor_sync(0xffffffffu, s2, off);
  }
  const float mean = s * (1.f / D_);
  const float var  = s2 * (1.f / D_) - mean * mean;
  const float inv  = rsqrtf(var + EPS_);
  float4* op = (float4*)(out + row * D_);
#pragma unroll
  for (int i = 0; i < 8; i++) {
    float4 gm = ((const float4*)gamma)[lane + i * 32];
    float4 bb = ((const float4*)beta)[lane + i * 32];
    float4 o;
    o.x = (v[i].x - mean) * inv * gm.x + bb.x;
    o.y = (v[i].y - mean) * inv * gm.y + bb.y;
    o.z = (v[i].z - mean) * inv * gm.z + bb.z;
    o.w = (v[i].w - mean) * inv * gm.w + bb.w;
    op[lane + i * 32] = tf32x4(o);
  }
}

// ============================================================
// Flash attention, bf16 m16n8k16. QT=128, KT=64, 8 warps,
// each warp owns 16 query rows. Q fragments direct from gmem.
// K rows / V s-pair rows cp.async double-buffered, raw bf16.
// Register softmax (fp32). One block barrier per KV tile.
// ============================================================
#define QT 128
#define KTT 64
#define NKT (S_ / KTT)
#define LKW 68    // words per K row (128 bf16 + 8 pad)
#define LVW 136   // words per V s-pair row (256 bf16 + 16 pad)
#define LPW 36    // words per P row (64 bf16 + 8 pad)
#define ATTN_SMEM ((2 * 64 * LKW + 2 * 32 * LVW + QT * LPW) * 4)

__global__ void __launch_bounds__(256) k_attn(const __nv_bfloat16* __restrict__ Qg,
                                              const __nv_bfloat16* __restrict__ Kg,
                                              const __nv_bfloat16* __restrict__ Vg,
                                              const float* __restrict__ modin,
                                              float* __restrict__ modout) {
  extern __shared__ float sm[];
  float* k_s = sm;                                  // [2][64][LKW] words
  float* v_s = sm + 2 * 64 * LKW;                   // [2][32][LVW] words
  uint32_t* p_s = (uint32_t*)(sm + 2 * 64 * LKW + 2 * 32 * LVW);  // [128][LPW]

  const int t = threadIdx.x;
  const int lane = t & 31, w = t >> 5;
  const int g = lane >> 2, tg = lane & 3;
  const int row0 = w * 16;

  const int q0 = blockIdx.x * QT;
  const int h = blockIdx.y, b = blockIdx.z;
  const size_t bh = (size_t)b * H_ + h;

  const float* Kp = (const float*)(Kg + bh * S_ * E_);   // word view
  const float* Vp = (const float*)(Vg + bh * S_ * E_);

  // ---- Q fragments straight from gmem (bf16 words) ----
  uint32_t qf[8][4];
  {
    const uint32_t* qw = (const uint32_t*)(Qg + (bh * S_ + q0) * E_);
#pragma unroll
    for (int kk = 0; kk < 8; kk++) {
      qf[kk][0] = qw[(row0 + g) * 64 + kk * 8 + tg];
      qf[kk][1] = qw[(row0 + g + 8) * 64 + kk * 8 + tg];
      qf[kk][2] = qw[(row0 + g) * 64 + kk * 8 + 4 + tg];
      qf[kk][3] = qw[(row0 + g + 8) * 64 + kk * 8 + 4 + tg];
    }
  }

  // ---- cp.async loaders ----
  // K: 64 rows x 64 words (16 chunks of 4 words); 4 chunks/thread
  const int k_r = t >> 2, k_c = t & 3;
  // V: 32 pair-rows x 128 words (32 chunks); 4 chunks/thread
  const int v_r = t >> 3, v_c = t & 7;

  auto load_kv = [&](int st, int kt) {
    float* ks = k_s + st * 64 * LKW;
    float* vs = v_s + st * 32 * LVW;
    const float* kb = Kp + (size_t)kt * KTT * 64;   // 64 words per key row
    const float* vb = Vp + (size_t)kt * 32 * 128;   // 128 words per pair row
#pragma unroll
    for (int i = 0; i < 4; i++) {
      int c = (k_c + i * 4) * 4;
      cp16(&ks[k_r * LKW + c], kb + (size_t)k_r * 64 + c);
    }
#pragma unroll
    for (int i = 0; i < 4; i++) {
      int c = (v_c + i * 8) * 4;
      cp16(&vs[v_r * LVW + c], vb + (size_t)v_r * 128 + c);
    }
  };

  load_kv(0, 0);
  CP_COMMIT();

  float o[16][4];
#pragma unroll
  for (int j = 0; j < 16; j++)
#pragma unroll
    for (int r = 0; r < 4; r++) o[j][r] = 0.f;

  float mA = -1e30f, mB = -1e30f, lA = 0.f, lB = 0.f;

  for (int kt = 0; kt < NKT; kt++) {
    const int cur = kt & 1;
    CP_WAIT0();
    __syncthreads();
    if (kt + 1 < NKT) {
      load_kv(cur ^ 1, kt + 1);
      CP_COMMIT();
    }
    const uint32_t* ksw = (const uint32_t*)(k_s + cur * 64 * LKW);
    const uint32_t* vsw = (const uint32_t*)(v_s + cur * 32 * LVW);

    // ---- phase A: scores (16 x 64) = Q K^T, k16 steps ----
    float sc[8][4];
#pragma unroll
    for (int j = 0; j < 8; j++)
#pragma unroll
      for (int r = 0; r < 4; r++) sc[j][r] = 0.f;

#pragma unroll
    for (int kk = 0; kk < 8; kk++) {
      uint32_t bf[8][2];
#pragma unroll
      for (int j = 0; j < 8; j++) {
        bf[j][0] = ksw[(j * 8 + g) * LKW + kk * 8 + tg];
        bf[j][1] = ksw[(j * 8 + g) * LKW + kk * 8 + 4 + tg];
      }
#pragma unroll
      for (int j = 0; j < 8; j++) mma_bf16(sc[j], qf[kk], bf[j]);
    }

    // ---- register softmax (fp32) ----
    {
      float mtA = -1e30f, mtB = -1e30f;
#pragma unroll
      for (int j = 0; j < 8; j++) {
        mtA = fmaxf(mtA, fmaxf(sc[j][0], sc[j][1]));
        mtB = fmaxf(mtB, fmaxf(sc[j][2], sc[j][3]));
      }
      mtA = fmaxf(mtA, __shfl_xor_sync(0xffffffffu, mtA, 1));
      mtA = fmaxf(mtA, __shfl_xor_sync(0xffffffffu, mtA, 2));
      mtB = fmaxf(mtB, __shfl_xor_sync(0xffffffffu, mtB, 1));
      mtB = fmaxf(mtB, __shfl_xor_sync(0xffffffffu, mtB, 2));
      float mnA = fmaxf(mA, mtA), mnB = fmaxf(mB, mtB);
      float aA = __expf(mA - mnA), aB = __expf(mB - mnB);
      mA = mnA; mB = mnB;
      float sA = 0.f, sB = 0.f;
#pragma unroll
      for (int j = 0; j < 8; j++) {
        sc[j][0] = __expf(sc[j][0] - mnA);
        sc[j][1] = __expf(sc[j][1] - mnA);
        sc[j][2] = __expf(sc[j][2] - mnB);
        sc[j][3] = __expf(sc[j][3] - mnB);
        sA += sc[j][0] + sc[j][1];
        sB += sc[j][2] + sc[j][3];
      }
      sA += __shfl_xor_sync(0xffffffffu, sA, 1);
      sA += __shfl_xor_sync(0xffffffffu, sA, 2);
      sB += __shfl_xor_sync(0xffffffffu, sB, 1);
      sB += __shfl_xor_sync(0xffffffffu, sB, 2);
      lA = lA * aA + sA;
      lB = lB * aB + sB;
#pragma unroll
      for (int j = 0; j < 16; j++) {
        o[j][0] *= aA; o[j][1] *= aA;
        o[j][2] *= aB; o[j][3] *= aB;
      }
    }

    // ---- write P (bf16x2) to warp-private smem rows ----
#pragma unroll
    for (int j = 0; j < 8; j++) {
      p_s[(row0 + g) * LPW + j * 4 + tg]     = packbf(sc[j][0], sc[j][1]);
      p_s[(row0 + g + 8) * LPW + j * 4 + tg] = packbf(sc[j][2], sc[j][3]);
    }
    __syncwarp();

    // ---- phase B: O (16 x 128) += P V, k16 steps ----
#pragma unroll
    for (int kk = 0; kk < 4; kk++) {
      uint32_t af[4];
      af[0] = p_s[(row0 + g) * LPW + kk * 8 + tg];
      af[1] = p_s[(row0 + g + 8) * LPW + kk * 8 + tg];
      af[2] = p_s[(row0 + g) * LPW + kk * 8 + 4 + tg];
      af[3] = p_s[(row0 + g + 8) * LPW + kk * 8 + 4 + tg];
      uint32_t bf[16][2];
#pragma unroll
      for (int j = 0; j < 16; j++) {
        bf[j][0] = vsw[(kk * 8 + tg) * LVW + j * 8 + g];
        bf[j][1] = vsw[(kk * 8 + 4 + tg) * LVW + j * 8 + g];
      }
#pragma unroll
      for (int j = 0; j < 16; j++) mma_bf16(o[j], af, bf[j]);
    }
  }

  // ---- epilogue: normalize + residual (fp32) ----
  {
    float invA = 1.f / lA, invB = 1.f / lB;
    const int rA = q0 + row0 + g, rB = rA + 8;
#pragma unroll
    for (int j = 0; j < 16; j++) {
      int c = j * 8 + 2 * tg;
      size_t baseA = ((size_t)b * S_ + rA) * D_ + (size_t)h * E_ + c;
      size_t baseB = ((size_t)b * S_ + rB) * D_ + (size_t)h * E_ + c;
      float2 mAv = *(const float2*)(modin + baseA);
      float2 mBv = *(const float2*)(modin + baseB);
      float2 oA = make_float2(mAv.x + o[j][0] * invA, mAv.y + o[j][1] * invA);
      float2 oB = make_float2(mBv.x + o[j][2] * invB, mBv.y + o[j][3] * invB);
      *(float2*)(modout + baseA) = oA;
      *(float2*)(modout + baseB) = oB;
    }
  }
}

// ============================================================
extern "C" void kernel_launch(void* const* d_in, const int* in_sizes, int n_in,
                              void* d_out, int out_size) {
  const float* x     = (const float*)d_in[0];
  const float* W_in  = (const float*)d_in[1];
  const float* gamma = (const float*)d_in[2];
  const float* beta  = (const float*)d_in[3];
  const float* Wq    = (const float*)d_in[4];
  const float* Wk    = (const float*)d_in[5];
  const float* Wv    = (const float*)d_in[6];
  const float* Wf    = (const float*)d_in[7];
  const float* bf    = (const float*)d_in[8];
  float* out = (float*)d_out;

  float *mod, *h, *q, *k, *v, *mod2, *h2;
  float *xt, *wint, *wft, *wqt, *wkt, *wvt;
  cudaGetSymbolAddress((void**)&mod,  g_mod);
  cudaGetSymbolAddress((void**)&h,    g_h);
  cudaGetSymbolAddress((void**)&q,    g_q);
  cudaGetSymbolAddress((void**)&k,    g_k);
  cudaGetSymbolAddress((void**)&v,    g_v);
  cudaGetSymbolAddress((void**)&mod2, g_mod2);
  cudaGetSymbolAddress((void**)&h2,   g_h2);
  cudaGetSymbolAddress((void**)&xt,   g_xt);
  cudaGetSymbolAddress((void**)&wint, g_wint);
  cudaGetSymbolAddress((void**)&wft,  g_wft);
  cudaGetSymbolAddress((void**)&wqt,  g_wqt);
  cudaGetSymbolAddress((void**)&wkt,  g_wkt);
  cudaGetSymbolAddress((void**)&wvt,  g_wvt);

  __nv_bfloat16* qb = (__nv_bfloat16*)q;
  __nv_bfloat16* kb = (__nv_bfloat16*)k;
  __nv_bfloat16* vb = (__nv_bfloat16*)v;

  cudaFuncSetAttribute(k_gemm_dense, cudaFuncAttributeMaxDynamicSharedMemorySize, GEMM_SMEM);
  cudaFuncSetAttribute(k_gemm_ffn,   cudaFuncAttributeMaxDynamicSharedMemorySize, GEMM_SMEM);
  cudaFuncSetAttribute(k_gemm_qkv,   cudaFuncAttributeMaxDynamicSharedMemorySize, GEMM_SMEM);
  cudaFuncSetAttribute(k_attn,       cudaFuncAttributeMaxDynamicSharedMemorySize, ATTN_SMEM);

  // ---- prep: RNA tf32 conversions ----
  k_cvt<<<(NT_ * D_ / 4 + 255) / 256, 256>>>(x, xt, NT_ * D_ / 4);
  k_cvt<<<(D_ * D_ / 4 + 255) / 256, 256>>>(W_in, wint, D_ * D_ / 4);
  k_cvt<<<(D_ * D_ / 4 + 255) / 256, 256>>>(Wf, wft, D_ * D_ / 4);
  dim3 g3((H_ * E_ * E_ / 4 + 255) / 256, 3);
  k_cvt3<<<g3, 256>>>(Wq, Wk, Wv, wqt, wkt, wvt, H_ * E_ * E_ / 4);

  dim3 gdense(D_ / GBN, NT_ / GBM);     // (8, 64)
  k_gemm_dense<<<gdense, 256, GEMM_SMEM>>>(xt, wint, mod);

  k_ln<<<NT_ / 8, 256>>>(mod, h, gamma, beta);

  dim3 gqkv(S_ / GBM, B_ * H_, 3);      // (16, 32, 3)
  k_gemm_qkv<<<gqkv, 256, GEMM_SMEM>>>(h, wqt, wkt, wvt, qb, kb, vb);

  dim3 gattn(S_ / QT, H_, B_);          // (16, 8, 4)
  k_attn<<<gattn, 256, ATTN_SMEM>>>(qb, kb, vb, mod, mod2);

  k_ln<<<NT_ / 8, 256>>>(mod2, h2, gamma, beta);

  k_gemm_ffn<<<gdense, 256, GEMM_SMEM>>>(h2, wft, bf, mod2, out);
}

// round 15
// speedup vs baseline: 1.7581x; 1.0522x over previous
#include <cuda_runtime.h>
#include <cuda_bf16.h>
#include <math.h>
#include <stdint.h>

// ---------------- problem constants ----------------
#define D_   1024
#define H_   8
#define E_   128
#define B_   4
#define S_   2048
#define NT_  (B_ * S_)
#define EPS_ 1e-6f

// ---------------- device scratch ----------------
__device__ float g_mod [NT_ * D_];
__device__ float g_h   [NT_ * D_];
__device__ float g_q   [NT_ * D_];   // used as bf16
__device__ float g_k   [NT_ * D_];
__device__ float g_v   [NT_ * D_];
__device__ float g_mod2[NT_ * D_];
__device__ float g_h2  [NT_ * D_];
__device__ float g_xt  [NT_ * D_];
__device__ float g_wint[D_ * D_];
__device__ float g_wft [D_ * D_];
__device__ float g_wqt [H_ * E_ * E_];
__device__ float g_wkt [H_ * E_ * E_];
__device__ float g_wvt [H_ * E_ * E_];

__device__ __forceinline__ float elu1(float x) { return x > 0.f ? x : expm1f(x); }

__device__ __forceinline__ float f2tf(float f) {
  uint32_t u;
  asm("cvt.rna.tf32.f32 %0, %1;" : "=r"(u) : "f"(f));
  return __uint_as_float(u);
}
__device__ __forceinline__ float4 tf32x4(float4 v) {
  return make_float4(f2tf(v.x), f2tf(v.y), f2tf(v.z), f2tf(v.w));
}
__device__ __forceinline__ uint32_t packbf(float lo, float hi) {
  __nv_bfloat162 p = __floats2bfloat162_rn(lo, hi);
  return *(uint32_t*)&p;
}

__device__ __forceinline__ void mma_tf32(float* d, const uint32_t* a, const uint32_t* b) {
  asm volatile(
      "mma.sync.aligned.m16n8k8.row.col.f32.tf32.tf32.f32 "
      "{%0,%1,%2,%3}, {%4,%5,%6,%7}, {%8,%9}, {%0,%1,%2,%3};"
      : "+f"(d[0]), "+f"(d[1]), "+f"(d[2]), "+f"(d[3])
      : "r"(a[0]), "r"(a[1]), "r"(a[2]), "r"(a[3]), "r"(b[0]), "r"(b[1]));
}
__device__ __forceinline__ void mma_bf16(float* d, const uint32_t* a, const uint32_t* b) {
  asm volatile(
      "mma.sync.aligned.m16n8k16.row.col.f32.bf16.bf16.f32 "
      "{%0,%1,%2,%3}, {%4,%5,%6,%7}, {%8,%9}, {%0,%1,%2,%3};"
      : "+f"(d[0]), "+f"(d[1]), "+f"(d[2]), "+f"(d[3])
      : "r"(a[0]), "r"(a[1]), "r"(a[2]), "r"(a[3]), "r"(b[0]), "r"(b[1]));
}
__device__ __forceinline__ void ldsm4(uint32_t* r, uint32_t a) {
  asm volatile("ldmatrix.sync.aligned.m8n8.x4.shared.b16 {%0,%1,%2,%3}, [%4];"
               : "=r"(r[0]), "=r"(r[1]), "=r"(r[2]), "=r"(r[3]) : "r"(a));
}

__device__ __forceinline__ void cp16(float* s, const float* g) {
  uint32_t sa = (uint32_t)__cvta_generic_to_shared(s);
  asm volatile("cp.async.cg.shared.global [%0], [%1], 16;" :: "r"(sa), "l"(g));
}
#define CP_COMMIT() asm volatile("cp.async.commit_group;")
#define CP_WAIT0()  asm volatile("cp.async.wait_group 0;")
#define CP_WAIT1()  asm volatile("cp.async.wait_group 1;")

// ============================================================
// prep: elementwise RNA tf32 conversion
// ============================================================
__global__ void k_cvt(const float* __restrict__ in, float* __restrict__ out, int n4) {
  int i = blockIdx.x * blockDim.x + threadIdx.x;
  if (i < n4) ((float4*)out)[i] = tf32x4(((const float4*)in)[i]);
}
__global__ void k_cvt3(const float* __restrict__ a, const float* __restrict__ b,
                       const float* __restrict__ c, float* __restrict__ oa,
                       float* __restrict__ ob, float* __restrict__ oc, int n4) {
  int i = blockIdx.x * blockDim.x + threadIdx.x;
  if (i >= n4) return;
  const float* in = blockIdx.y == 0 ? a : (blockIdx.y == 1 ? b : c);
  float* out = blockIdx.y == 0 ? oa : (blockIdx.y == 1 ? ob : oc);
  ((float4*)out)[i] = tf32x4(((const float4*)in)[i]);
}

// ============================================================
// TF32 GEMM, 3-stage cp.async pipeline (unchanged from R12/13).
// MODE: 0 fp32 out, 1 fp32+bias/ELU/resid, 2 bf16 out,
//       3 bf16 out rows pair-interleaved (V).
// ============================================================
#define GBM 128
#define GBN 128
#define GBK 32
#define LDA_S 36
#define LDB_S 136
#define ST_SZ (GBM * LDA_S + GBK * LDB_S)
#define GEMM_SMEM (3 * ST_SZ * 4)

template <int MODE>
__device__ __forceinline__ void gemm_core(
    const float* __restrict__ A, int lda,
    const float* __restrict__ Bm, int ldb,
    void* __restrict__ Cv, int ldc, int K,
    const float* __restrict__ bias, const float* __restrict__ resid) {
  extern __shared__ float smg[];

  const int t = threadIdx.x;
  const int lane = t & 31, wid = t >> 5;
  const int g = lane >> 2, tg = lane & 3;
  const int wr = wid >> 2, wc = wid & 3;

  const int a_r = t >> 3;
  const int a_c = (t & 7) * 4;
  const int b_r = t >> 5;
  const int b_c = (t & 31) * 4;

  float acc[4][4][4];
#pragma unroll
  for (int i = 0; i < 4; i++)
#pragma unroll
    for (int j = 0; j < 4; j++)
#pragma unroll
      for (int r = 0; r < 4; r++) acc[i][j][r] = 0.f;

  auto load_stage = [&](int st, int k0) {
    float* as = smg + st * ST_SZ;
    float* bs = as + GBM * LDA_S;
#pragma unroll
    for (int i = 0; i < 4; i++) {
      int r = a_r + i * 32;
      cp16(&as[r * LDA_S + a_c], A + (size_t)r * lda + k0 + a_c);
    }
#pragma unroll
    for (int i = 0; i < 4; i++) {
      int r = b_r + i * 8;
      cp16(&bs[r * LDB_S + b_c], Bm + (size_t)(k0 + r) * ldb + b_c);
    }
  };

  load_stage(0, 0);
  CP_COMMIT();
  if (GBK < K) {
    load_stage(1, GBK);
    CP_COMMIT();
  }

  int cur = 0;
  for (int k0 = 0; k0 < K; k0 += GBK) {
    CP_WAIT1();
    __syncthreads();
    if (k0 + 2 * GBK < K) {
      int nxt = cur + 2; if (nxt >= 3) nxt -= 3;
      load_stage(nxt, k0 + 2 * GBK);
      CP_COMMIT();
    }
    const uint32_t* as = (const uint32_t*)(smg + cur * ST_SZ);
    const uint32_t* bs = as + GBM * LDA_S;
#pragma unroll
    for (int kk = 0; kk < GBK; kk += 8) {
      uint32_t af[4][4], bf[4][2];
#pragma unroll
      for (int i = 0; i < 4; i++) {
        int r0 = wr * 64 + i * 16;
        af[i][0] = as[(r0 + g) * LDA_S + kk + tg];
        af[i][1] = as[(r0 + g + 8) * LDA_S + kk + tg];
        af[i][2] = as[(r0 + g) * LDA_S + kk + tg + 4];
        af[i][3] = as[(r0 + g + 8) * LDA_S + kk + tg + 4];
      }
#pragma unroll
      for (int j = 0; j < 4; j++) {
        int c0 = wc * 32 + j * 8;
        bf[j][0] = bs[(kk + tg) * LDB_S + c0 + g];
        bf[j][1] = bs[(kk + tg + 4) * LDB_S + c0 + g];
      }
#pragma unroll
      for (int i = 0; i < 4; i++)
#pragma unroll
        for (int j = 0; j < 4; j++) mma_tf32(acc[i][j], af[i], bf[j]);
    }
    if (++cur == 3) cur = 0;
  }

  // epilogue
#pragma unroll
  for (int i = 0; i < 4; i++) {
    int rA = wr * 64 + i * 16 + g;
    int rB = rA + 8;
#pragma unroll
    for (int j = 0; j < 4; j++) {
      int c = wc * 32 + j * 8 + 2 * tg;
      float2 o0 = make_float2(acc[i][j][0], acc[i][j][1]);
      float2 o1 = make_float2(acc[i][j][2], acc[i][j][3]);
      if (MODE == 1) {
        float2 bv = *(const float2*)(bias + c);
        float2 r0 = *(const float2*)(resid + (size_t)rA * ldc + c);
        float2 r1 = *(const float2*)(resid + (size_t)rB * ldc + c);
        o0.x = r0.x + elu1(o0.x + bv.x);
        o0.y = r0.y + elu1(o0.y + bv.y);
        o1.x = r1.x + elu1(o1.x + bv.x);
        o1.y = r1.y + elu1(o1.y + bv.y);
      }
      if (MODE <= 1) {
        float* C = (float*)Cv;
        *(float2*)(C + (size_t)rA * ldc + c) = o0;
        *(float2*)(C + (size_t)rB * ldc + c) = o1;
      } else if (MODE == 2) {
        uint32_t* C = (uint32_t*)Cv;
        C[(size_t)rA * (ldc / 2) + (c >> 1)] = packbf(o0.x, o0.y);
        C[(size_t)rB * (ldc / 2) + (c >> 1)] = packbf(o1.x, o1.y);
      } else {
        __nv_bfloat16* C = (__nv_bfloat16*)Cv;
        size_t pA = (size_t)(rA >> 1) * 2 * ldc + 2 * c + (rA & 1);
        size_t pB = (size_t)(rB >> 1) * 2 * ldc + 2 * c + (rB & 1);
        C[pA]     = __float2bfloat16_rn(o0.x);
        C[pA + 2] = __float2bfloat16_rn(o0.y);
        C[pB]     = __float2bfloat16_rn(o1.x);
        C[pB + 2] = __float2bfloat16_rn(o1.y);
      }
    }
  }
}

__global__ void __launch_bounds__(256) k_gemm_dense(const float* __restrict__ A,
                                                    const float* __restrict__ W,
                                                    float* __restrict__ C) {
  const size_t moff = (size_t)blockIdx.y * GBM * D_;
  gemm_core<0>(A + moff, D_, W + blockIdx.x * GBN, D_,
               C + moff + blockIdx.x * GBN, D_, D_, nullptr, nullptr);
}

__global__ void __launch_bounds__(256) k_gemm_ffn(const float* __restrict__ A,
                                                  const float* __restrict__ W,
                                                  const float* __restrict__ bias,
                                                  const float* __restrict__ resid,
                                                  float* __restrict__ C) {
  const size_t moff = (size_t)blockIdx.y * GBM * D_;
  const size_t off = moff + blockIdx.x * GBN;
  gemm_core<1>(A + moff, D_, W + blockIdx.x * GBN, D_, C + off, D_, D_,
               bias + blockIdx.x * GBN, resid + off);
}

__global__ void __launch_bounds__(256) k_gemm_qkv(const float* __restrict__ Hm,
                                                  const float* __restrict__ Wq,
                                                  const float* __restrict__ Wk,
                                                  const float* __restrict__ Wv,
                                                  __nv_bfloat16* __restrict__ Oq,
                                                  __nv_bfloat16* __restrict__ Ok,
                                                  __nv_bfloat16* __restrict__ Ov) {
  const int which = blockIdx.z;
  const int bh = blockIdx.y;
  const int b = bh >> 3, h = bh & 7;
  const float* A = Hm + ((size_t)b * S_ + (size_t)blockIdx.x * GBM) * D_ + h * E_;
  if (which == 0) {
    __nv_bfloat16* C = Oq + ((size_t)bh * S_ + (size_t)blockIdx.x * GBM) * E_;
    gemm_core<2>(A, D_, Wq + h * E_ * E_, E_, C, E_, E_, nullptr, nullptr);
  } else if (which == 1) {
    __nv_bfloat16* C = Ok + ((size_t)bh * S_ + (size_t)blockIdx.x * GBM) * E_;
    gemm_core<2>(A, D_, Wk + h * E_ * E_, E_, C, E_, E_, nullptr, nullptr);
  } else {
    __nv_bfloat16* C = Ov + ((size_t)bh * S_ + (size_t)blockIdx.x * GBM) * E_;
    gemm_core<3>(A, D_, Wv + h * E_ * E_, E_, C, E_, E_, nullptr, nullptr);
  }
}

// ============================================================
// LayerNorm, warp-per-row (8 rows/block); tf32 output.
// ============================================================
__global__ void __launch_bounds__(256) k_ln(const float* __restrict__ in,
                                            float* __restrict__ out,
                                            const float* __restrict__ gamma,
                                            const float* __restrict__ beta) {
  const int lane = threadIdx.x & 31;
  const size_t row = (size_t)blockIdx.x * 8 + (threadIdx.x >> 5);
  const float4* ip = (const float4*)(in + row * D_);
  float4 v[8];
  float s = 0.f, s2 = 0.f;
#pragma unroll
  for (int i = 0; i < 8; i++) {
    v[i] = ip[lane + i * 32];
    s  += v[i].x + v[i].y + v[i].z + v[i].w;
    s2 += v[i].x * v[i].x + v[i].y * v[i].y + v[i].z * v[i].z + v[i].w * v[i].w;
  }
#pragma unroll
  for (int off = 16; off; off >>= 1) {
    s  += __shfl_xor_sync(0xffffffffu, s, off);
    s2 += __shfl_xor_sync(0xffffffffu, s2, off);
  }
  const float mean = s * (1.f / D_);
  const float var  = s2 * (1.f / D_) - mean * mean;
  const float inv  = rsqrtf(var + EPS_);
  float4* op = (float4*)(out + row * D_);
#pragma unroll
  for (int i = 0; i < 8; i++) {
    float4 gm = ((const float4*)gamma)[lane + i * 32];
    float4 bb = ((const float4*)beta)[lane + i * 32];
    float4 o;
    o.x = (v[i].x - mean) * inv * gm.x + bb.x;
    o.y = (v[i].y - mean) * inv * gm.y + bb.y;
    o.z = (v[i].z - mean) * inv * gm.z + bb.z;
    o.w = (v[i].w - mean) * inv * gm.w + bb.w;
    op[lane + i * 32] = tf32x4(o);
  }
}

// ============================================================
// Flash attention, bf16 m16n8k16. QT=128, KT=64, 8 warps.
// P stays in registers (accumulator layout == A-fragment layout
// after packbf). K B-fragments via non-trans ldmatrix.x4.
// cp.async double-buffered K/V, one block barrier per tile.
// ============================================================
#define QT 128
#define KTT 64
#define NKT (S_ / KTT)
#define LKW 68    // words per K row (128 bf16 + 8 pad)
#define LVW 136   // words per V s-pair row (256 bf16 + 16 pad)
#define ATTN_SMEM ((2 * 64 * LKW + 2 * 32 * LVW) * 4)

__global__ void __launch_bounds__(256) k_attn(const __nv_bfloat16* __restrict__ Qg,
                                              const __nv_bfloat16* __restrict__ Kg,
                                              const __nv_bfloat16* __restrict__ Vg,
                                              const float* __restrict__ modin,
                                              float* __restrict__ modout) {
  extern __shared__ float sm[];
  float* k_s = sm;                                  // [2][64][LKW] words
  float* v_s = sm + 2 * 64 * LKW;                   // [2][32][LVW] words

  const int t = threadIdx.x;
  const int lane = t & 31, w = t >> 5;
  const int g = lane >> 2, tg = lane & 3;
  const int row0 = w * 16;

  const int q0 = blockIdx.x * QT;
  const int h = blockIdx.y, b = blockIdx.z;
  const size_t bh = (size_t)b * H_ + h;

  const float* Kp = (const float*)(Kg + bh * S_ * E_);
  const float* Vp = (const float*)(Vg + bh * S_ * E_);

  // ---- Q fragments straight from gmem ----
  uint32_t qf[8][4];
  {
    const uint32_t* qw = (const uint32_t*)(Qg + (bh * S_ + q0) * E_);
#pragma unroll
    for (int kk = 0; kk < 8; kk++) {
      qf[kk][0] = qw[(row0 + g) * 64 + kk * 8 + tg];
      qf[kk][1] = qw[(row0 + g + 8) * 64 + kk * 8 + tg];
      qf[kk][2] = qw[(row0 + g) * 64 + kk * 8 + 4 + tg];
      qf[kk][3] = qw[(row0 + g + 8) * 64 + kk * 8 + 4 + tg];
    }
  }

  // ---- ldmatrix base addresses for K fragments ----
  // tile layout per jp: sec0 -> bf[2jp][0], sec1 -> bf[2jp][1],
  //                     sec2 -> bf[2jp+1][0], sec3 -> bf[2jp+1][1]
  uint32_t ka_base[4];
  {
    uint32_t kaddr = (uint32_t)__cvta_generic_to_shared(k_s);
    const int sec = lane >> 3, l = lane & 7;
    const int roff = sec >> 1, woff = (sec & 1) * 4;
#pragma unroll
    for (int jp = 0; jp < 4; jp++) {
      int row = (2 * jp + roff) * 8 + l;
      ka_base[jp] = kaddr + 4 * (row * LKW + woff);
    }
  }

  // ---- cp.async loaders ----
  const int k_r = t >> 2, k_c = t & 3;
  const int v_r = t >> 3, v_c = t & 7;

  auto load_kv = [&](int st, int kt) {
    float* ks = k_s + st * 64 * LKW;
    float* vs = v_s + st * 32 * LVW;
    const float* kb = Kp + (size_t)kt * KTT * 64;
    const float* vb = Vp + (size_t)kt * 32 * 128;
#pragma unroll
    for (int i = 0; i < 4; i++) {
      int c = (k_c + i * 4) * 4;
      cp16(&ks[k_r * LKW + c], kb + (size_t)k_r * 64 + c);
    }
#pragma unroll
    for (int i = 0; i < 4; i++) {
      int c = (v_c + i * 8) * 4;
      cp16(&vs[v_r * LVW + c], vb + (size_t)v_r * 128 + c);
    }
  };

  load_kv(0, 0);
  CP_COMMIT();

  float o[16][4];
#pragma unroll
  for (int j = 0; j < 16; j++)
#pragma unroll
    for (int r = 0; r < 4; r++) o[j][r] = 0.f;

  float mA = -1e30f, mB = -1e30f, lA = 0.f, lB = 0.f;

  for (int kt = 0; kt < NKT; kt++) {
    const int cur = kt & 1;
    CP_WAIT0();
    __syncthreads();
    if (kt + 1 < NKT) {
      load_kv(cur ^ 1, kt + 1);
      CP_COMMIT();
    }
    const uint32_t kst = (uint32_t)(cur * 64 * LKW * 4);
    const uint32_t* vsw = (const uint32_t*)(v_s + cur * 32 * LVW);

    // ---- phase A: scores (16 x 64) = Q K^T via ldmatrix ----
    float sc[8][4];
#pragma unroll
    for (int j = 0; j < 8; j++)
#pragma unroll
      for (int r = 0; r < 4; r++) sc[j][r] = 0.f;

#pragma unroll
    for (int kk = 0; kk < 8; kk++) {
#pragma unroll
      for (int jp = 0; jp < 4; jp++) {
        uint32_t bfr[4];
        ldsm4(bfr, ka_base[jp] + kst + kk * 32);
        mma_bf16(sc[2 * jp],     qf[kk], bfr);
        mma_bf16(sc[2 * jp + 1], qf[kk], bfr + 2);
      }
    }

    // ---- register softmax (fp32) ----
    {
      float mtA = -1e30f, mtB = -1e30f;
#pragma unroll
      for (int j = 0; j < 8; j++) {
        mtA = fmaxf(mtA, fmaxf(sc[j][0], sc[j][1]));
        mtB = fmaxf(mtB, fmaxf(sc[j][2], sc[j][3]));
      }
      mtA = fmaxf(mtA, __shfl_xor_sync(0xffffffffu, mtA, 1));
      mtA = fmaxf(mtA, __shfl_xor_sync(0xffffffffu, mtA, 2));
      mtB = fmaxf(mtB, __shfl_xor_sync(0xffffffffu, mtB, 1));
      mtB = fmaxf(mtB, __shfl_xor_sync(0xffffffffu, mtB, 2));
      float mnA = fmaxf(mA, mtA), mnB = fmaxf(mB, mtB);
      float aA = __expf(mA - mnA), aB = __expf(mB - mnB);
      mA = mnA; mB = mnB;
      float sA = 0.f, sB = 0.f;
#pragma unroll
      for (int j = 0; j < 8; j++) {
        sc[j][0] = __expf(sc[j][0] - mnA);
        sc[j][1] = __expf(sc[j][1] - mnA);
        sc[j][2] = __expf(sc[j][2] - mnB);
        sc[j][3] = __expf(sc[j][3] - mnB);
        sA += sc[j][0] + sc[j][1];
        sB += sc[j][2] + sc[j][3];
      }
      sA += __shfl_xor_sync(0xffffffffu, sA, 1);
      sA += __shfl_xor_sync(0xffffffffu, sA, 2);
      sB += __shfl_xor_sync(0xffffffffu, sB, 1);
      sB += __shfl_xor_sync(0xffffffffu, sB, 2);
      lA = lA * aA + sA;
      lB = lB * aB + sB;
#pragma unroll
      for (int j = 0; j < 16; j++) {
        o[j][0] *= aA; o[j][1] *= aA;
        o[j][2] *= aB; o[j][3] *= aB;
      }
    }

    // ---- phase B: O += P V, P packed directly from registers ----
#pragma unroll
    for (int kk = 0; kk < 4; kk++) {
      uint32_t af[4];
      af[0] = packbf(sc[2 * kk][0],     sc[2 * kk][1]);
      af[1] = packbf(sc[2 * kk][2],     sc[2 * kk][3]);
      af[2] = packbf(sc[2 * kk + 1][0], sc[2 * kk + 1][1]);
      af[3] = packbf(sc[2 * kk + 1][2], sc[2 * kk + 1][3]);
      uint32_t bf[16][2];
#pragma unroll
      for (int j = 0; j < 16; j++) {
        bf[j][0] = vsw[(kk * 8 + tg) * LVW + j * 8 + g];
        bf[j][1] = vsw[(kk * 8 + 4 + tg) * LVW + j * 8 + g];
      }
#pragma unroll
      for (int j = 0; j < 16; j++) mma_bf16(o[j], af, bf[j]);
    }
  }

  // ---- epilogue: normalize + residual (fp32) ----
  {
    float invA = 1.f / lA, invB = 1.f / lB;
    const int rA = q0 + row0 + g, rB = rA + 8;
#pragma unroll
    for (int j = 0; j < 16; j++) {
      int c = j * 8 + 2 * tg;
      size_t baseA = ((size_t)b * S_ + rA) * D_ + (size_t)h * E_ + c;
      size_t baseB = ((size_t)b * S_ + rB) * D_ + (size_t)h * E_ + c;
      float2 mAv = *(const float2*)(modin + baseA);
      float2 mBv = *(const float2*)(modin + baseB);
      float2 oA = make_float2(mAv.x + o[j][0] * invA, mAv.y + o[j][1] * invA);
      float2 oB = make_float2(mBv.x + o[j][2] * invB, mBv.y + o[j][3] * invB);
      *(float2*)(modout + baseA) = oA;
      *(float2*)(modout + baseB) = oB;
    }
  }
}

// ============================================================
extern "C" void kernel_launch(void* const* d_in, const int* in_sizes, int n_in,
                              void* d_out, int out_size) {
  const float* x     = (const float*)d_in[0];
  const float* W_in  = (const float*)d_in[1];
  const float* gamma = (const float*)d_in[2];
  const float* beta  = (const float*)d_in[3];
  const float* Wq    = (const float*)d_in[4];
  const float* Wk    = (const float*)d_in[5];
  const float* Wv    = (const float*)d_in[6];
  const float* Wf    = (const float*)d_in[7];
  const float* bf    = (const float*)d_in[8];
  float* out = (float*)d_out;

  float *mod, *h, *q, *k, *v, *mod2, *h2;
  float *xt, *wint, *wft, *wqt, *wkt, *wvt;
  cudaGetSymbolAddress((void**)&mod,  g_mod);
  cudaGetSymbolAddress((void**)&h,    g_h);
  cudaGetSymbolAddress((void**)&q,    g_q);
  cudaGetSymbolAddress((void**)&k,    g_k);
  cudaGetSymbolAddress((void**)&v,    g_v);
  cudaGetSymbolAddress((void**)&mod2, g_mod2);
  cudaGetSymbolAddress((void**)&h2,   g_h2);
  cudaGetSymbolAddress((void**)&xt,   g_xt);
  cudaGetSymbolAddress((void**)&wint, g_wint);
  cudaGetSymbolAddress((void**)&wft,  g_wft);
  cudaGetSymbolAddress((void**)&wqt,  g_wqt);
  cudaGetSymbolAddress((void**)&wkt,  g_wkt);
  cudaGetSymbolAddress((void**)&wvt,  g_wvt);

  __nv_bfloat16* qb = (__nv_bfloat16*)q;
  __nv_bfloat16* kb = (__nv_bfloat16*)k;
  __nv_bfloat16* vb = (__nv_bfloat16*)v;

  cudaFuncSetAttribute(k_gemm_dense, cudaFuncAttributeMaxDynamicSharedMemorySize, GEMM_SMEM);
  cudaFuncSetAttribute(k_gemm_ffn,   cudaFuncAttributeMaxDynamicSharedMemorySize, GEMM_SMEM);
  cudaFuncSetAttribute(k_gemm_qkv,   cudaFuncAttributeMaxDynamicSharedMemorySize, GEMM_SMEM);
  cudaFuncSetAttribute(k_attn,       cudaFuncAttributeMaxDynamicSharedMemorySize, ATTN_SMEM);

  // ---- prep: RNA tf32 conversions ----
  k_cvt<<<(NT_ * D_ / 4 + 255) / 256, 256>>>(x, xt, NT_ * D_ / 4);
  k_cvt<<<(D_ * D_ / 4 + 255) / 256, 256>>>(W_in, wint, D_ * D_ / 4);
  k_cvt<<<(D_ * D_ / 4 + 255) / 256, 256>>>(Wf, wft, D_ * D_ / 4);
  dim3 g3((H_ * E_ * E_ / 4 + 255) / 256, 3);
  k_cvt3<<<g3, 256>>>(Wq, Wk, Wv, wqt, wkt, wvt, H_ * E_ * E_ / 4);

  dim3 gdense(D_ / GBN, NT_ / GBM);     // (8, 64)
  k_gemm_dense<<<gdense, 256, GEMM_SMEM>>>(xt, wint, mod);

  k_ln<<<NT_ / 8, 256>>>(mod, h, gamma, beta);

  dim3 gqkv(S_ / GBM, B_ * H_, 3);      // (16, 32, 3)
  k_gemm_qkv<<<gqkv, 256, GEMM_SMEM>>>(h, wqt, wkt, wvt, qb, kb, vb);

  dim3 gattn(S_ / QT, H_, B_);          // (16, 8, 4)
  k_attn<<<gattn, 256, ATTN_SMEM>>>(qb, kb, vb, mod, mod2);

  k_ln<<<NT_ / 8, 256>>>(mod2, h2, gamma, beta);

  k_gemm_ffn<<<gdense, 256, GEMM_SMEM>>>(h2, wft, bf, mod2, out);
}

// round 16
// speedup vs baseline: 1.8226x; 1.0367x over previous
#include <cuda_runtime.h>
#include <cuda_bf16.h>
#include <math.h>
#include <stdint.h>

// ---------------- problem constants ----------------
#define D_   1024
#define H_   8
#define E_   128
#define B_   4
#define S_   2048
#define NT_  (B_ * S_)
#define EPS_ 1e-6f

// ---------------- device scratch ----------------
__device__ float g_mod [NT_ * D_];
__device__ float g_h   [NT_ * D_];   // bf16 (half used)
__device__ float g_q   [NT_ * D_];   // bf16
__device__ float g_k   [NT_ * D_];
__device__ float g_v   [NT_ * D_];
__device__ float g_mod2[NT_ * D_];
__device__ float g_h2  [NT_ * D_];
__device__ float g_xt  [NT_ * D_];
__device__ float g_wint[D_ * D_];
__device__ float g_wft [D_ * D_];
__device__ float g_wqt [H_ * E_ * E_];  // bf16 pair-interleaved (half used)
__device__ float g_wkt [H_ * E_ * E_];
__device__ float g_wvt [H_ * E_ * E_];

__device__ __forceinline__ float elu1(float x) { return x > 0.f ? x : expm1f(x); }

__device__ __forceinline__ float f2tf(float f) {
  uint32_t u;
  asm("cvt.rna.tf32.f32 %0, %1;" : "=r"(u) : "f"(f));
  return __uint_as_float(u);
}
__device__ __forceinline__ float4 tf32x4(float4 v) {
  return make_float4(f2tf(v.x), f2tf(v.y), f2tf(v.z), f2tf(v.w));
}
__device__ __forceinline__ uint32_t packbf(float lo, float hi) {
  __nv_bfloat162 p = __floats2bfloat162_rn(lo, hi);
  return *(uint32_t*)&p;
}

__device__ __forceinline__ void mma_tf32(float* d, const uint32_t* a, const uint32_t* b) {
  asm volatile(
      "mma.sync.aligned.m16n8k8.row.col.f32.tf32.tf32.f32 "
      "{%0,%1,%2,%3}, {%4,%5,%6,%7}, {%8,%9}, {%0,%1,%2,%3};"
      : "+f"(d[0]), "+f"(d[1]), "+f"(d[2]), "+f"(d[3])
      : "r"(a[0]), "r"(a[1]), "r"(a[2]), "r"(a[3]), "r"(b[0]), "r"(b[1]));
}
__device__ __forceinline__ void mma_bf16(float* d, const uint32_t* a, const uint32_t* b) {
  asm volatile(
      "mma.sync.aligned.m16n8k16.row.col.f32.bf16.bf16.f32 "
      "{%0,%1,%2,%3}, {%4,%5,%6,%7}, {%8,%9}, {%0,%1,%2,%3};"
      : "+f"(d[0]), "+f"(d[1]), "+f"(d[2]), "+f"(d[3])
      : "r"(a[0]), "r"(a[1]), "r"(a[2]), "r"(a[3]), "r"(b[0]), "r"(b[1]));
}
__device__ __forceinline__ void ldsm4(uint32_t* r, uint32_t a) {
  asm volatile("ldmatrix.sync.aligned.m8n8.x4.shared.b16 {%0,%1,%2,%3}, [%4];"
               : "=r"(r[0]), "=r"(r[1]), "=r"(r[2]), "=r"(r[3]) : "r"(a));
}

__device__ __forceinline__ void cp16(float* s, const float* g) {
  uint32_t sa = (uint32_t)__cvta_generic_to_shared(s);
  asm volatile("cp.async.cg.shared.global [%0], [%1], 16;" :: "r"(sa), "l"(g));
}
#define CP_COMMIT() asm volatile("cp.async.commit_group;")
#define CP_WAIT0()  asm volatile("cp.async.wait_group 0;")
#define CP_WAIT1()  asm volatile("cp.async.wait_group 1;")

// ============================================================
// prep kernels
// ============================================================
__global__ void k_cvt(const float* __restrict__ in, float* __restrict__ out, int n4) {
  int i = blockIdx.x * blockDim.x + threadIdx.x;
  if (i < n4) ((float4*)out)[i] = tf32x4(((const float4*)in)[i]);
}

// head weights -> bf16 pair-interleaved: word i (per head) holds
// {W[2pr][n], W[2pr+1][n]} with pr = i/128, n = i%128.
__global__ void k_cvtw3(const float* __restrict__ a, const float* __restrict__ b,
                        const float* __restrict__ c, uint32_t* __restrict__ oa,
                        uint32_t* __restrict__ ob, uint32_t* __restrict__ oc) {
  int i = blockIdx.x * blockDim.x + threadIdx.x;   // word index, H*E*E/2 total
  const float* in = blockIdx.y == 0 ? a : (blockIdx.y == 1 ? b : c);
  uint32_t* out = blockIdx.y == 0 ? oa : (blockIdx.y == 1 ? ob : oc);
  int head = i >> 13;                // 8192 words per head
  int loc = i & 8191;
  int pr = loc >> 7, n = loc & 127;
  const float* W = in + head * E_ * E_;
  out[i] = packbf(W[(2 * pr) * E_ + n], W[(2 * pr + 1) * E_ + n]);
}

// ============================================================
// TF32 GEMM, 3-stage cp.async pipeline (dense / FFN only).
// MODE: 0 fp32 out, 1 fp32 + bias/ELU/residual.
// ============================================================
#define GBM 128
#define GBN 128
#define GBK 32
#define LDA_S 36
#define LDB_S 136
#define ST_SZ (GBM * LDA_S + GBK * LDB_S)
#define GEMM_SMEM (3 * ST_SZ * 4)

template <int MODE>
__device__ __forceinline__ void gemm_core(
    const float* __restrict__ A, int lda,
    const float* __restrict__ Bm, int ldb,
    float* __restrict__ C, int ldc, int K,
    const float* __restrict__ bias, const float* __restrict__ resid) {
  extern __shared__ float smg[];

  const int t = threadIdx.x;
  const int lane = t & 31, wid = t >> 5;
  const int g = lane >> 2, tg = lane & 3;
  const int wr = wid >> 2, wc = wid & 3;

  const int a_r = t >> 3;
  const int a_c = (t & 7) * 4;
  const int b_r = t >> 5;
  const int b_c = (t & 31) * 4;

  float acc[4][4][4];
#pragma unroll
  for (int i = 0; i < 4; i++)
#pragma unroll
    for (int j = 0; j < 4; j++)
#pragma unroll
      for (int r = 0; r < 4; r++) acc[i][j][r] = 0.f;

  auto load_stage = [&](int st, int k0) {
    float* as = smg + st * ST_SZ;
    float* bs = as + GBM * LDA_S;
#pragma unroll
    for (int i = 0; i < 4; i++) {
      int r = a_r + i * 32;
      cp16(&as[r * LDA_S + a_c], A + (size_t)r * lda + k0 + a_c);
    }
#pragma unroll
    for (int i = 0; i < 4; i++) {
      int r = b_r + i * 8;
      cp16(&bs[r * LDB_S + b_c], Bm + (size_t)(k0 + r) * ldb + b_c);
    }
  };

  load_stage(0, 0);
  CP_COMMIT();
  load_stage(1, GBK);
  CP_COMMIT();

  int cur = 0;
  for (int k0 = 0; k0 < K; k0 += GBK) {
    CP_WAIT1();
    __syncthreads();
    if (k0 + 2 * GBK < K) {
      int nxt = cur + 2; if (nxt >= 3) nxt -= 3;
      load_stage(nxt, k0 + 2 * GBK);
      CP_COMMIT();
    }
    const uint32_t* as = (const uint32_t*)(smg + cur * ST_SZ);
    const uint32_t* bs = as + GBM * LDA_S;
#pragma unroll
    for (int kk = 0; kk < GBK; kk += 8) {
      uint32_t af[4][4], bf[4][2];
#pragma unroll
      for (int i = 0; i < 4; i++) {
        int r0 = wr * 64 + i * 16;
        af[i][0] = as[(r0 + g) * LDA_S + kk + tg];
        af[i][1] = as[(r0 + g + 8) * LDA_S + kk + tg];
        af[i][2] = as[(r0 + g) * LDA_S + kk + tg + 4];
        af[i][3] = as[(r0 + g + 8) * LDA_S + kk + tg + 4];
      }
#pragma unroll
      for (int j = 0; j < 4; j++) {
        int c0 = wc * 32 + j * 8;
        bf[j][0] = bs[(kk + tg) * LDB_S + c0 + g];
        bf[j][1] = bs[(kk + tg + 4) * LDB_S + c0 + g];
      }
#pragma unroll
      for (int i = 0; i < 4; i++)
#pragma unroll
        for (int j = 0; j < 4; j++) mma_tf32(acc[i][j], af[i], bf[j]);
    }
    if (++cur == 3) cur = 0;
  }

#pragma unroll
  for (int i = 0; i < 4; i++) {
    int rA = wr * 64 + i * 16 + g;
    int rB = rA + 8;
#pragma unroll
    for (int j = 0; j < 4; j++) {
      int c = wc * 32 + j * 8 + 2 * tg;
      float2 o0 = make_float2(acc[i][j][0], acc[i][j][1]);
      float2 o1 = make_float2(acc[i][j][2], acc[i][j][3]);
      if (MODE == 1) {
        float2 bv = *(const float2*)(bias + c);
        float2 r0 = *(const float2*)(resid + (size_t)rA * ldc + c);
        float2 r1 = *(const float2*)(resid + (size_t)rB * ldc + c);
        o0.x = r0.x + elu1(o0.x + bv.x);
        o0.y = r0.y + elu1(o0.y + bv.y);
        o1.x = r1.x + elu1(o1.x + bv.x);
        o1.y = r1.y + elu1(o1.y + bv.y);
      }
      *(float2*)(C + (size_t)rA * ldc + c) = o0;
      *(float2*)(C + (size_t)rB * ldc + c) = o1;
    }
  }
}

__global__ void __launch_bounds__(256) k_gemm_dense(const float* __restrict__ A,
                                                    const float* __restrict__ W,
                                                    float* __restrict__ C) {
  const size_t moff = (size_t)blockIdx.y * GBM * D_;
  gemm_core<0>(A + moff, D_, W + blockIdx.x * GBN, D_,
               C + moff + blockIdx.x * GBN, D_, D_, nullptr, nullptr);
}

__global__ void __launch_bounds__(256) k_gemm_ffn(const float* __restrict__ A,
                                                  const float* __restrict__ W,
                                                  const float* __restrict__ bias,
                                                  const float* __restrict__ resid,
                                                  float* __restrict__ C) {
  const size_t moff = (size_t)blockIdx.y * GBM * D_;
  const size_t off = moff + blockIdx.x * GBN;
  gemm_core<1>(A + moff, D_, W + blockIdx.x * GBN, D_, C + off, D_, D_,
               bias + blockIdx.x * GBN, resid + off);
}

// ============================================================
// bf16 QKV GEMM: 128x128, K=128 single stage, 8 warps (2x4).
// A = h bf16 row-major (64 words/row), B = weights bf16
// pair-interleaved (like V). One barrier total.
// WHICH: 0 = Q (bf16 out), 1 = K (bf16 out), 2 = V (pair-interleaved out)
// ============================================================
#define LAW 68
#define LBW 136
#define QKV_SMEM ((128 * LAW + 64 * LBW) * 4)

__global__ void __launch_bounds__(256) k_gemm_qkv(const float* __restrict__ Hm,
                                                  const float* __restrict__ Wq,
                                                  const float* __restrict__ Wk,
                                                  const float* __restrict__ Wv,
                                                  __nv_bfloat16* __restrict__ Oq,
                                                  __nv_bfloat16* __restrict__ Ok,
                                                  __nv_bfloat16* __restrict__ Ov) {
  extern __shared__ float smq[];
  float* a_s = smq;                 // [128][LAW] words
  float* b_s = smq + 128 * LAW;     // [64][LBW] words

  const int which = blockIdx.z;
  const int bh = blockIdx.y;
  const int b = bh >> 3, h = bh & 7;

  const int t = threadIdx.x;
  const int lane = t & 31, wid = t >> 5;
  const int g = lane >> 2, tg = lane & 3;
  const int wr = wid >> 2, wc = wid & 3;

  // A: rows of h (bf16 words: 512/row, head offset h*64)
  const float* Aw = Hm + ((size_t)b * S_ + (size_t)blockIdx.x * 128) * (D_ / 2) + h * 64;
  // B: weight head base (words)
  const float* Wsel = which == 0 ? Wq : (which == 1 ? Wk : Wv);
  const float* Bw = Wsel + (size_t)h * 8192;

  {
    const int ar = t >> 1;                 // 0..127
    const int ac0 = (t & 1) * 4;           // 0 or 4 (word)
#pragma unroll
    for (int i = 0; i < 8; i++) {
      int c = ac0 + i * 8;                 // 16 chunks of 4 words per row
      cp16(&a_s[ar * LAW + c], Aw + (size_t)ar * (D_ / 2) + c);
    }
    const int br = t >> 2;                 // 0..63
    const int bc0 = (t & 3) * 4;
#pragma unroll
    for (int i = 0; i < 8; i++) {
      int c = bc0 + i * 16;                // 32 chunks of 4 words per pair-row
      cp16(&b_s[br * LBW + c], Bw + (size_t)br * 128 + c);
    }
  }
  CP_COMMIT();
  CP_WAIT0();
  __syncthreads();

  float acc[4][4][4];
#pragma unroll
  for (int i = 0; i < 4; i++)
#pragma unroll
    for (int j = 0; j < 4; j++)
#pragma unroll
      for (int r = 0; r < 4; r++) acc[i][j][r] = 0.f;

  const uint32_t* asw = (const uint32_t*)a_s;
  const uint32_t* bsw = (const uint32_t*)b_s;
#pragma unroll
  for (int kk = 0; kk < 8; kk++) {
    uint32_t af[4][4], bf[4][2];
#pragma unroll
    for (int i = 0; i < 4; i++) {
      int r0 = wr * 64 + i * 16;
      af[i][0] = asw[(r0 + g) * LAW + kk * 8 + tg];
      af[i][1] = asw[(r0 + g + 8) * LAW + kk * 8 + tg];
      af[i][2] = asw[(r0 + g) * LAW + kk * 8 + 4 + tg];
      af[i][3] = asw[(r0 + g + 8) * LAW + kk * 8 + 4 + tg];
    }
#pragma unroll
    for (int j = 0; j < 4; j++) {
      int c0 = wc * 32 + j * 8;
      bf[j][0] = bsw[(kk * 8 + tg) * LBW + c0 + g];
      bf[j][1] = bsw[(kk * 8 + 4 + tg) * LBW + c0 + g];
    }
#pragma unroll
    for (int i = 0; i < 4; i++)
#pragma unroll
      for (int j = 0; j < 4; j++) mma_bf16(acc[i][j], af[i], bf[j]);
  }

  // epilogue
  __nv_bfloat16* Out = which == 0 ? Oq : (which == 1 ? Ok : Ov);
  __nv_bfloat16* C = Out + ((size_t)bh * S_ + (size_t)blockIdx.x * 128) * E_;
#pragma unroll
  for (int i = 0; i < 4; i++) {
    int rA = wr * 64 + i * 16 + g;
    int rB = rA + 8;
#pragma unroll
    for (int j = 0; j < 4; j++) {
      int c = wc * 32 + j * 8 + 2 * tg;
      if (which < 2) {
        uint32_t* Cw = (uint32_t*)C;
        Cw[(size_t)rA * 64 + (c >> 1)] = packbf(acc[i][j][0], acc[i][j][1]);
        Cw[(size_t)rB * 64 + (c >> 1)] = packbf(acc[i][j][2], acc[i][j][3]);
      } else {
        size_t pA = (size_t)(rA >> 1) * 2 * E_ + 2 * c + (rA & 1);
        size_t pB = (size_t)(rB >> 1) * 2 * E_ + 2 * c + (rB & 1);
        C[pA]     = __float2bfloat16_rn(acc[i][j][0]);
        C[pA + 2] = __float2bfloat16_rn(acc[i][j][1]);
        C[pB]     = __float2bfloat16_rn(acc[i][j][2]);
        C[pB + 2] = __float2bfloat16_rn(acc[i][j][3]);
      }
    }
  }
}

// ============================================================
// LayerNorm, warp-per-row. BF16OUT: packed bf16 (for h), else tf32.
// ============================================================
template <bool BF16OUT>
__global__ void __launch_bounds__(256) k_ln(const float* __restrict__ in,
                                            float* __restrict__ out,
                                            const float* __restrict__ gamma,
                                            const float* __restrict__ beta) {
  const int lane = threadIdx.x & 31;
  const size_t row = (size_t)blockIdx.x * 8 + (threadIdx.x >> 5);
  const float4* ip = (const float4*)(in + row * D_);
  float4 v[8];
  float s = 0.f, s2 = 0.f;
#pragma unroll
  for (int i = 0; i < 8; i++) {
    v[i] = ip[lane + i * 32];
    s  += v[i].x + v[i].y + v[i].z + v[i].w;
    s2 += v[i].x * v[i].x + v[i].y * v[i].y + v[i].z * v[i].z + v[i].w * v[i].w;
  }
#pragma unroll
  for (int off = 16; off; off >>= 1) {
    s  += __shfl_xor_sync(0xffffffffu, s, off);
    s2 += __shfl_xor_sync(0xffffffffu, s2, off);
  }
  const float mean = s * (1.f / D_);
  const float var  = s2 * (1.f / D_) - mean * mean;
  const float inv  = rsqrtf(var + EPS_);
#pragma unroll
  for (int i = 0; i < 8; i++) {
    float4 gm = ((const float4*)gamma)[lane + i * 32];
    float4 bb = ((const float4*)beta)[lane + i * 32];
    float4 o;
    o.x = (v[i].x - mean) * inv * gm.x + bb.x;
    o.y = (v[i].y - mean) * inv * gm.y + bb.y;
    o.z = (v[i].z - mean) * inv * gm.z + bb.z;
    o.w = (v[i].w - mean) * inv * gm.w + bb.w;
    if (BF16OUT) {
      uint2 pw = make_uint2(packbf(o.x, o.y), packbf(o.z, o.w));
      ((uint2*)(out + row * (D_ / 2)))[lane + i * 32] = pw;
    } else {
      ((float4*)(out + row * D_))[lane + i * 32] = tf32x4(o);
    }
  }
}

// ============================================================
// Flash attention (R14 structure, unchanged).
// ============================================================
#define QT 128
#define KTT 64
#define NKT (S_ / KTT)
#define LKW 68
#define LVW 136
#define ATTN_SMEM ((2 * 64 * LKW + 2 * 32 * LVW) * 4)

__global__ void __launch_bounds__(256) k_attn(const __nv_bfloat16* __restrict__ Qg,
                                              const __nv_bfloat16* __restrict__ Kg,
                                              const __nv_bfloat16* __restrict__ Vg,
                                              const float* __restrict__ modin,
                                              float* __restrict__ modout) {
  extern __shared__ float sm[];
  float* k_s = sm;
  float* v_s = sm + 2 * 64 * LKW;

  const int t = threadIdx.x;
  const int lane = t & 31, w = t >> 5;
  const int g = lane >> 2, tg = lane & 3;
  const int row0 = w * 16;

  const int q0 = blockIdx.x * QT;
  const int h = blockIdx.y, b = blockIdx.z;
  const size_t bh = (size_t)b * H_ + h;

  const float* Kp = (const float*)(Kg + bh * S_ * E_);
  const float* Vp = (const float*)(Vg + bh * S_ * E_);

  uint32_t qf[8][4];
  {
    const uint32_t* qw = (const uint32_t*)(Qg + (bh * S_ + q0) * E_);
#pragma unroll
    for (int kk = 0; kk < 8; kk++) {
      qf[kk][0] = qw[(row0 + g) * 64 + kk * 8 + tg];
      qf[kk][1] = qw[(row0 + g + 8) * 64 + kk * 8 + tg];
      qf[kk][2] = qw[(row0 + g) * 64 + kk * 8 + 4 + tg];
      qf[kk][3] = qw[(row0 + g + 8) * 64 + kk * 8 + 4 + tg];
    }
  }

  uint32_t ka_base[4];
  {
    uint32_t kaddr = (uint32_t)__cvta_generic_to_shared(k_s);
    const int sec = lane >> 3, l = lane & 7;
    const int roff = sec >> 1, woff = (sec & 1) * 4;
#pragma unroll
    for (int jp = 0; jp < 4; jp++) {
      int row = (2 * jp + roff) * 8 + l;
      ka_base[jp] = kaddr + 4 * (row * LKW + woff);
    }
  }

  const int k_r = t >> 2, k_c = t & 3;
  const int v_r = t >> 3, v_c = t & 7;

  auto load_kv = [&](int st, int kt) {
    float* ks = k_s + st * 64 * LKW;
    float* vs = v_s + st * 32 * LVW;
    const float* kb = Kp + (size_t)kt * KTT * 64;
    const float* vb = Vp + (size_t)kt * 32 * 128;
#pragma unroll
    for (int i = 0; i < 4; i++) {
      int c = (k_c + i * 4) * 4;
      cp16(&ks[k_r * LKW + c], kb + (size_t)k_r * 64 + c);
    }
#pragma unroll
    for (int i = 0; i < 4; i++) {
      int c = (v_c + i * 8) * 4;
      cp16(&vs[v_r * LVW + c], vb + (size_t)v_r * 128 + c);
    }
  };

  load_kv(0, 0);
  CP_COMMIT();

  float o[16][4];
#pragma unroll
  for (int j = 0; j < 16; j++)
#pragma unroll
    for (int r = 0; r < 4; r++) o[j][r] = 0.f;

  float mA = -1e30f, mB = -1e30f, lA = 0.f, lB = 0.f;

  for (int kt = 0; kt < NKT; kt++) {
    const int cur = kt & 1;
    CP_WAIT0();
    __syncthreads();
    if (kt + 1 < NKT) {
      load_kv(cur ^ 1, kt + 1);
      CP_COMMIT();
    }
    const uint32_t kst = (uint32_t)(cur * 64 * LKW * 4);
    const uint32_t* vsw = (const uint32_t*)(v_s + cur * 32 * LVW);

    float sc[8][4];
#pragma unroll
    for (int j = 0; j < 8; j++)
#pragma unroll
      for (int r = 0; r < 4; r++) sc[j][r] = 0.f;

#pragma unroll
    for (int kk = 0; kk < 8; kk++) {
#pragma unroll
      for (int jp = 0; jp < 4; jp++) {
        uint32_t bfr[4];
        ldsm4(bfr, ka_base[jp] + kst + kk * 32);
        mma_bf16(sc[2 * jp],     qf[kk], bfr);
        mma_bf16(sc[2 * jp + 1], qf[kk], bfr + 2);
      }
    }

    {
      float mtA = -1e30f, mtB = -1e30f;
#pragma unroll
      for (int j = 0; j < 8; j++) {
        mtA = fmaxf(mtA, fmaxf(sc[j][0], sc[j][1]));
        mtB = fmaxf(mtB, fmaxf(sc[j][2], sc[j][3]));
      }
      mtA = fmaxf(mtA, __shfl_xor_sync(0xffffffffu, mtA, 1));
      mtA = fmaxf(mtA, __shfl_xor_sync(0xffffffffu, mtA, 2));
      mtB = fmaxf(mtB, __shfl_xor_sync(0xffffffffu, mtB, 1));
      mtB = fmaxf(mtB, __shfl_xor_sync(0xffffffffu, mtB, 2));
      float mnA = fmaxf(mA, mtA), mnB = fmaxf(mB, mtB);
      float aA = __expf(mA - mnA), aB = __expf(mB - mnB);
      mA = mnA; mB = mnB;
      float sA = 0.f, sB = 0.f;
#pragma unroll
      for (int j = 0; j < 8; j++) {
        sc[j][0] = __expf(sc[j][0] - mnA);
        sc[j][1] = __expf(sc[j][1] - mnA);
        sc[j][2] = __expf(sc[j][2] - mnB);
        sc[j][3] = __expf(sc[j][3] - mnB);
        sA += sc[j][0] + sc[j][1];
        sB += sc[j][2] + sc[j][3];
      }
      sA += __shfl_xor_sync(0xffffffffu, sA, 1);
      sA += __shfl_xor_sync(0xffffffffu, sA, 2);
      sB += __shfl_xor_sync(0xffffffffu, sB, 1);
      sB += __shfl_xor_sync(0xffffffffu, sB, 2);
      lA = lA * aA + sA;
      lB = lB * aB + sB;
#pragma unroll
      for (int j = 0; j < 16; j++) {
        o[j][0] *= aA; o[j][1] *= aA;
        o[j][2] *= aB; o[j][3] *= aB;
      }
    }

#pragma unroll
    for (int kk = 0; kk < 4; kk++) {
      uint32_t af[4];
      af[0] = packbf(sc[2 * kk][0],     sc[2 * kk][1]);
      af[1] = packbf(sc[2 * kk][2],     sc[2 * kk][3]);
      af[2] = packbf(sc[2 * kk + 1][0], sc[2 * kk + 1][1]);
      af[3] = packbf(sc[2 * kk + 1][2], sc[2 * kk + 1][3]);
      uint32_t bf[16][2];
#pragma unroll
      for (int j = 0; j < 16; j++) {
        bf[j][0] = vsw[(kk * 8 + tg) * LVW + j * 8 + g];
        bf[j][1] = vsw[(kk * 8 + 4 + tg) * LVW + j * 8 + g];
      }
#pragma unroll
      for (int j = 0; j < 16; j++) mma_bf16(o[j], af, bf[j]);
    }
  }

  {
    float invA = 1.f / lA, invB = 1.f / lB;
    const int rA = q0 + row0 + g, rB = rA + 8;
#pragma unroll
    for (int j = 0; j < 16; j++) {
      int c = j * 8 + 2 * tg;
      size_t baseA = ((size_t)b * S_ + rA) * D_ + (size_t)h * E_ + c;
      size_t baseB = ((size_t)b * S_ + rB) * D_ + (size_t)h * E_ + c;
      float2 mAv = *(const float2*)(modin + baseA);
      float2 mBv = *(const float2*)(modin + baseB);
      float2 oA = make_float2(mAv.x + o[j][0] * invA, mAv.y + o[j][1] * invA);
      float2 oB = make_float2(mBv.x + o[j][2] * invB, mBv.y + o[j][3] * invB);
      *(float2*)(modout + baseA) = oA;
      *(float2*)(modout + baseB) = oB;
    }
  }
}

// ============================================================
extern "C" void kernel_launch(void* const* d_in, const int* in_sizes, int n_in,
                              void* d_out, int out_size) {
  const float* x     = (const float*)d_in[0];
  const float* W_in  = (const float*)d_in[1];
  const float* gamma = (const float*)d_in[2];
  const float* beta  = (const float*)d_in[3];
  const float* Wq    = (const float*)d_in[4];
  const float* Wk    = (const float*)d_in[5];
  const float* Wv    = (const float*)d_in[6];
  const float* Wf    = (const float*)d_in[7];
  const float* bf    = (const float*)d_in[8];
  float* out = (float*)d_out;

  float *mod, *h, *q, *k, *v, *mod2, *h2;
  float *xt, *wint, *wft, *wqt, *wkt, *wvt;
  cudaGetSymbolAddress((void**)&mod,  g_mod);
  cudaGetSymbolAddress((void**)&h,    g_h);
  cudaGetSymbolAddress((void**)&q,    g_q);
  cudaGetSymbolAddress((void**)&k,    g_k);
  cudaGetSymbolAddress((void**)&v,    g_v);
  cudaGetSymbolAddress((void**)&mod2, g_mod2);
  cudaGetSymbolAddress((void**)&h2,   g_h2);
  cudaGetSymbolAddress((void**)&xt,   g_xt);
  cudaGetSymbolAddress((void**)&wint, g_wint);
  cudaGetSymbolAddress((void**)&wft,  g_wft);
  cudaGetSymbolAddress((void**)&wqt,  g_wqt);
  cudaGetSymbolAddress((void**)&wkt,  g_wkt);
  cudaGetSymbolAddress((void**)&wvt,  g_wvt);

  __nv_bfloat16* qb = (__nv_bfloat16*)q;
  __nv_bfloat16* kb = (__nv_bfloat16*)k;
  __nv_bfloat16* vb = (__nv_bfloat16*)v;

  cudaFuncSetAttribute(k_gemm_dense, cudaFuncAttributeMaxDynamicSharedMemorySize, GEMM_SMEM);
  cudaFuncSetAttribute(k_gemm_ffn,   cudaFuncAttributeMaxDynamicSharedMemorySize, GEMM_SMEM);
  cudaFuncSetAttribute(k_gemm_qkv,   cudaFuncAttributeMaxDynamicSharedMemorySize, QKV_SMEM);
  cudaFuncSetAttribute(k_attn,       cudaFuncAttributeMaxDynamicSharedMemorySize, ATTN_SMEM);

  // ---- prep conversions ----
  k_cvt<<<(NT_ * D_ / 4 + 255) / 256, 256>>>(x, xt, NT_ * D_ / 4);
  k_cvt<<<(D_ * D_ / 4 + 255) / 256, 256>>>(W_in, wint, D_ * D_ / 4);
  k_cvt<<<(D_ * D_ / 4 + 255) / 256, 256>>>(Wf, wft, D_ * D_ / 4);
  dim3 gw((H_ * E_ * E_ / 2 + 255) / 256, 3);
  k_cvtw3<<<gw, 256>>>(Wq, Wk, Wv, (uint32_t*)wqt, (uint32_t*)wkt, (uint32_t*)wvt);

  dim3 gdense(D_ / GBN, NT_ / GBM);     // (8, 64)
  k_gemm_dense<<<gdense, 256, GEMM_SMEM>>>(xt, wint, mod);

  k_ln<true><<<NT_ / 8, 256>>>(mod, h, gamma, beta);   // h as bf16

  dim3 gqkv(S_ / GBM, B_ * H_, 3);      // (16, 32, 3)
  k_gemm_qkv<<<gqkv, 256, QKV_SMEM>>>(h, wqt, wkt, wvt, qb, kb, vb);

  dim3 gattn(S_ / QT, H_, B_);          // (16, 8, 4)
  k_attn<<<gattn, 256, ATTN_SMEM>>>(qb, kb, vb, mod, mod2);

  k_ln<false><<<NT_ / 8, 256>>>(mod2, h2, gamma, beta);

  k_gemm_ffn<<<gdense, 256, GEMM_SMEM>>>(h2, wft, bf, mod2, out);
}